// round 4
// baseline (speedup 1.0000x reference)
#include <cuda_runtime.h>
#include <cuda_fp16.h>
#include <cstdint>

#define BATCH 2
#define SEQ   2048
#define HDIM  1024
#define NHEAD 16
#define HD    64
#define MROWS (BATCH * SEQ)   // 4096

// ---------------- scratch (device globals: allocation-free) ------------------
__device__ __half g_Qh[MROWS * HDIM];
__device__ __half g_Kh[MROWS * HDIM];
__device__ __half g_Vh[MROWS * HDIM];
__device__ float  g_AO[MROWS * HDIM];
__device__ float  g_Y[MROWS * HDIM];

// ---------------- helpers ----------------------------------------------------
__device__ __forceinline__ uint32_t f2tf32(float x) {
    uint32_t u;
    asm("cvt.rna.tf32.f32 %0, %1;" : "=r"(u) : "f"(x));
    return u;
}

__device__ __forceinline__ void mma1688(float* c, const uint32_t* a, const uint32_t* b) {
    asm volatile(
        "mma.sync.aligned.m16n8k8.row.col.f32.tf32.tf32.f32 "
        "{%0,%1,%2,%3},{%4,%5,%6,%7},{%8,%9},{%0,%1,%2,%3};"
        : "+f"(c[0]), "+f"(c[1]), "+f"(c[2]), "+f"(c[3])
        : "r"(a[0]), "r"(a[1]), "r"(a[2]), "r"(a[3]), "r"(b[0]), "r"(b[1]));
}

__device__ __forceinline__ void mma16816h(float* c, const uint32_t* a, const uint32_t* b) {
    asm volatile(
        "mma.sync.aligned.m16n8k16.row.col.f32.f16.f16.f32 "
        "{%0,%1,%2,%3},{%4,%5,%6,%7},{%8,%9},{%0,%1,%2,%3};"
        : "+f"(c[0]), "+f"(c[1]), "+f"(c[2]), "+f"(c[3])
        : "r"(a[0]), "r"(a[1]), "r"(a[2]), "r"(a[3]), "r"(b[0]), "r"(b[1]));
}

__device__ __forceinline__ void ldsm_x4(uint32_t& r0, uint32_t& r1, uint32_t& r2,
                                        uint32_t& r3, uint32_t addr) {
    asm volatile("ldmatrix.sync.aligned.m8n8.x4.shared.b16 {%0,%1,%2,%3}, [%4];"
                 : "=r"(r0), "=r"(r1), "=r"(r2), "=r"(r3) : "r"(addr));
}
__device__ __forceinline__ void ldsm_x4t(uint32_t& r0, uint32_t& r1, uint32_t& r2,
                                         uint32_t& r3, uint32_t addr) {
    asm volatile("ldmatrix.sync.aligned.m8n8.x4.trans.shared.b16 {%0,%1,%2,%3}, [%4];"
                 : "=r"(r0), "=r"(r1), "=r"(r2), "=r"(r3) : "r"(addr));
}

__device__ __forceinline__ void cp16(uint32_t dst, const void* src) {
    asm volatile("cp.async.cg.shared.global [%0], [%1], 16;" :: "r"(dst), "l"(src));
}
__device__ __forceinline__ void cp_commit_wait() {
    asm volatile("cp.async.commit_group;");
    asm volatile("cp.async.wait_group 0;");
}

// ---------------- TF32 tensor-core GEMM: C = A[M,K] @ W[N,K]^T + bias --------
#define GS 36

template <typename OutT>
__global__ void __launch_bounds__(256) gemm_tc(
    const float* __restrict__ A, const float* __restrict__ W,
    const float* __restrict__ bias, OutT* __restrict__ C,
    int M, int N, int K)
{
    __shared__ uint32_t As[128 * GS];
    __shared__ uint32_t Bs[128 * GS];

    const int tid  = threadIdx.x;
    const int w    = tid >> 5;
    const int lane = tid & 31;
    const int g    = lane >> 2;
    const int t    = lane & 3;
    const int wm   = (w >> 2) * 64;
    const int wn   = (w & 3) * 32;

    const int m0 = blockIdx.y * 128;
    const int n0 = blockIdx.x * 128;

    const int lr = tid >> 3;
    const int lc = (tid & 7) * 4;

    const float* Ap = A + (size_t)(m0 + lr) * K + lc;
    const float* Wp = W + (size_t)(n0 + lr) * K + lc;

    float acc[4][4][4];
    #pragma unroll
    for (int i = 0; i < 4; i++)
        #pragma unroll
        for (int j = 0; j < 4; j++)
            #pragma unroll
            for (int r = 0; r < 4; r++) acc[i][j][r] = 0.f;

    float4 ra[4], rb[4];
    #pragma unroll
    for (int p = 0; p < 4; p++) {
        ra[p] = *(const float4*)(Ap + (size_t)p * 32 * K);
        rb[p] = *(const float4*)(Wp + (size_t)p * 32 * K);
    }

    const int niter = K / 32;
    for (int kb = 0; kb < niter; kb++) {
        #pragma unroll
        for (int p = 0; p < 4; p++) {
            int row = lr + p * 32;
            uint32_t* pa = &As[row * GS + lc];
            pa[0] = f2tf32(ra[p].x); pa[1] = f2tf32(ra[p].y);
            pa[2] = f2tf32(ra[p].z); pa[3] = f2tf32(ra[p].w);
            uint32_t* pb = &Bs[row * GS + lc];
            pb[0] = f2tf32(rb[p].x); pb[1] = f2tf32(rb[p].y);
            pb[2] = f2tf32(rb[p].z); pb[3] = f2tf32(rb[p].w);
        }
        __syncthreads();

        if (kb + 1 < niter) {
            const float* Ap2 = Ap + (size_t)(kb + 1) * 32;
            const float* Wp2 = Wp + (size_t)(kb + 1) * 32;
            #pragma unroll
            for (int p = 0; p < 4; p++) {
                ra[p] = *(const float4*)(Ap2 + (size_t)p * 32 * K);
                rb[p] = *(const float4*)(Wp2 + (size_t)p * 32 * K);
            }
        }

        #pragma unroll
        for (int ks = 0; ks < 4; ks++) {
            const int k0 = ks * 8;
            uint32_t af[4][4], bf[4][2];
            #pragma unroll
            for (int mt = 0; mt < 4; mt++) {
                const int mb = wm + mt * 16;
                af[mt][0] = As[(mb + g) * GS + k0 + t];
                af[mt][1] = As[(mb + g + 8) * GS + k0 + t];
                af[mt][2] = As[(mb + g) * GS + k0 + t + 4];
                af[mt][3] = As[(mb + g + 8) * GS + k0 + t + 4];
            }
            #pragma unroll
            for (int nt = 0; nt < 4; nt++) {
                const int nb = wn + nt * 8;
                bf[nt][0] = Bs[(nb + g) * GS + k0 + t];
                bf[nt][1] = Bs[(nb + g) * GS + k0 + t + 4];
            }
            #pragma unroll
            for (int mt = 0; mt < 4; mt++)
                #pragma unroll
                for (int nt = 0; nt < 4; nt++)
                    mma1688(acc[mt][nt], af[mt], bf[nt]);
        }
        __syncthreads();
    }

    #pragma unroll
    for (int mt = 0; mt < 4; mt++) {
        const int row0 = m0 + wm + mt * 16 + g;
        const int row1 = row0 + 8;
        #pragma unroll
        for (int nt = 0; nt < 4; nt++) {
            const int col = n0 + wn + nt * 8 + t * 2;
            const float b0 = bias[col], b1 = bias[col + 1];
            float c00 = acc[mt][nt][0] + b0, c01 = acc[mt][nt][1] + b1;
            float c10 = acc[mt][nt][2] + b0, c11 = acc[mt][nt][3] + b1;
            if constexpr (sizeof(OutT) == 4) {
                *(float2*)((float*)C + (size_t)row0 * N + col) = make_float2(c00, c01);
                *(float2*)((float*)C + (size_t)row1 * N + col) = make_float2(c10, c11);
            } else {
                *(__half2*)((__half*)C + (size_t)row0 * N + col) = __floats2half2_rn(c00, c01);
                *(__half2*)((__half*)C + (size_t)row1 * N + col) = __floats2half2_rn(c10, c11);
            }
        }
    }
}

// ---------------- FA2-style fp16 flash attention (causal) --------------------
// Block: 128 q-rows (8 warps x 16 rows), K-tile 64. S and P live in registers.
#define KS_STR 72   // halves per smem row (144B: 16B-aligned, conflict-free ldsm)

__global__ void __launch_bounds__(256) attn_fa(
    const __half* __restrict__ Qh, const __half* __restrict__ Kh,
    const __half* __restrict__ Vh, float* __restrict__ O)
{
    __shared__ __half Ks[64 * KS_STR];
    __shared__ __half Vs[64 * KS_STR];

    const int tid  = threadIdx.x;
    const int w    = tid >> 5;
    const int lane = tid & 31;
    const int g    = lane >> 2;
    const int t    = lane & 3;
    const int wq   = w * 16;

    const int q0 = (gridDim.x - 1 - blockIdx.x) * 128;  // heavy blocks first
    const int h  = blockIdx.y;
    const int b  = blockIdx.z;

    const uint32_t ks_base = (uint32_t)__cvta_generic_to_shared(Ks);
    const uint32_t vs_base = (uint32_t)__cvta_generic_to_shared(Vs);

    // ---- stage Q tile [128][64] into (Ks|Vs) region, ldmatrix into regs ----
    const __half* Qg = Qh + ((size_t)(b * SEQ + q0)) * HDIM + h * HD;
    {
        #pragma unroll
        for (int j = 0; j < 4; j++) {
            int i = tid + j * 256;          // 0..1023 chunks of 8 halves
            int r = i >> 3;
            int c8 = (i & 7) * 8;
            cp16(ks_base + (r * KS_STR + c8) * 2, Qg + (size_t)r * HDIM + c8);
        }
        cp_commit_wait();
        __syncthreads();
    }

    uint32_t qf[4][4];  // 4 k-steps of A fragments (scaled by 1/8)
    {
        const __half2 sc = __half2half2(__float2half(0.125f));
        const int row = wq + (lane & 15);
        const int chi = (lane >> 4) * 8;
        #pragma unroll
        for (int ks = 0; ks < 4; ks++) {
            uint32_t addr = ks_base + (row * KS_STR + ks * 16 + chi) * 2;
            ldsm_x4(qf[ks][0], qf[ks][1], qf[ks][2], qf[ks][3], addr);
            #pragma unroll
            for (int r = 0; r < 4; r++) {
                __half2 v = *(__half2*)&qf[ks][r];
                v = __hmul2(v, sc);
                qf[ks][r] = *(uint32_t*)&v;
            }
        }
    }

    float m0r = -1e30f, m1r = -1e30f, l0r = 0.f, l1r = 0.f;
    float oacc[8][4];
    #pragma unroll
    for (int j = 0; j < 8; j++)
        #pragma unroll
        for (int r = 0; r < 4; r++) oacc[j][r] = 0.f;

    // ldmatrix lane addresses (precomputed components)
    const int kn_row = (lane & 7) + ((lane >> 4) & 1) * 8;   // K: n-row within 16-group
    const int kn_col = ((lane >> 3) & 1) * 8;                // K: k-col offset
    const int vk_row = (lane & 7) + ((lane >> 3) & 1) * 8;   // V: k-row within 16-step
    const int vn_col = (lane >> 4) * 8;                      // V: n-col offset

    const int jmax = (q0 + 127) / 64;
    for (int jt = 0; jt <= jmax; jt++) {
        const int k0g = jt * 64;
        const __half* Kg = Kh + ((size_t)(b * SEQ + k0g)) * HDIM + h * HD;
        const __half* Vg = Vh + ((size_t)(b * SEQ + k0g)) * HDIM + h * HD;

        __syncthreads();
        #pragma unroll
        for (int j = 0; j < 2; j++) {
            int i = tid + j * 256;          // 0..511 chunks
            int r = i >> 3;
            int c8 = (i & 7) * 8;
            cp16(ks_base + (r * KS_STR + c8) * 2, Kg + (size_t)r * HDIM + c8);
            cp16(vs_base + (r * KS_STR + c8) * 2, Vg + (size_t)r * HDIM + c8);
        }
        cp_commit_wait();
        __syncthreads();

        const bool active = (k0g <= q0 + wq + 15);
        if (active) {
            // ---- S = Q @ K^T : sacc[8 n-tiles][4] --------------------------
            float sacc[8][4];
            #pragma unroll
            for (int j = 0; j < 8; j++)
                #pragma unroll
                for (int r = 0; r < 4; r++) sacc[j][r] = 0.f;

            #pragma unroll
            for (int ks = 0; ks < 4; ks++) {
                #pragma unroll
                for (int ng = 0; ng < 4; ng++) {
                    uint32_t b0, b1, b2, b3;
                    uint32_t addr = ks_base +
                        ((ng * 16 + kn_row) * KS_STR + ks * 16 + kn_col) * 2;
                    ldsm_x4(b0, b1, b2, b3, addr);
                    uint32_t bf0[2] = {b0, b1}, bf1[2] = {b2, b3};
                    mma16816h(sacc[ng * 2],     qf[ks], bf0);
                    mma16816h(sacc[ng * 2 + 1], qf[ks], bf1);
                }
            }

            // ---- causal mask (only near diagonal) --------------------------
            if (k0g + 63 > q0 + wq) {
                const int row0 = q0 + wq + g;
                const int row1 = row0 + 8;
                #pragma unroll
                for (int j = 0; j < 8; j++) {
                    const int col = k0g + j * 8 + t * 2;
                    if (col > row0)     sacc[j][0] = -1e30f;
                    if (col + 1 > row0) sacc[j][1] = -1e30f;
                    if (col > row1)     sacc[j][2] = -1e30f;
                    if (col + 1 > row1) sacc[j][3] = -1e30f;
                }
            }

            // ---- online softmax (register + quad shuffle) ------------------
            float tm0 = -1e30f, tm1 = -1e30f;
            #pragma unroll
            for (int j = 0; j < 8; j++) {
                tm0 = fmaxf(tm0, fmaxf(sacc[j][0], sacc[j][1]));
                tm1 = fmaxf(tm1, fmaxf(sacc[j][2], sacc[j][3]));
            }
            tm0 = fmaxf(tm0, __shfl_xor_sync(0xffffffffu, tm0, 1));
            tm0 = fmaxf(tm0, __shfl_xor_sync(0xffffffffu, tm0, 2));
            tm1 = fmaxf(tm1, __shfl_xor_sync(0xffffffffu, tm1, 1));
            tm1 = fmaxf(tm1, __shfl_xor_sync(0xffffffffu, tm1, 2));

            const float mn0 = fmaxf(m0r, tm0);
            const float mn1 = fmaxf(m1r, tm1);
            const float al0 = __expf(m0r - mn0);
            const float al1 = __expf(m1r - mn1);
            m0r = mn0; m1r = mn1;

            float rs0 = 0.f, rs1 = 0.f;
            #pragma unroll
            for (int j = 0; j < 8; j++) {
                sacc[j][0] = __expf(sacc[j][0] - mn0);
                sacc[j][1] = __expf(sacc[j][1] - mn0);
                sacc[j][2] = __expf(sacc[j][2] - mn1);
                sacc[j][3] = __expf(sacc[j][3] - mn1);
                rs0 += sacc[j][0] + sacc[j][1];
                rs1 += sacc[j][2] + sacc[j][3];
            }
            rs0 += __shfl_xor_sync(0xffffffffu, rs0, 1);
            rs0 += __shfl_xor_sync(0xffffffffu, rs0, 2);
            rs1 += __shfl_xor_sync(0xffffffffu, rs1, 1);
            rs1 += __shfl_xor_sync(0xffffffffu, rs1, 2);
            l0r = l0r * al0 + rs0;
            l1r = l1r * al1 + rs1;

            // ---- P fragments (half2 pack, direct A-layout) -----------------
            uint32_t pa[4][4];
            #pragma unroll
            for (int ks = 0; ks < 4; ks++) {
                __half2 h0 = __floats2half2_rn(sacc[2*ks][0],   sacc[2*ks][1]);
                __half2 h1 = __floats2half2_rn(sacc[2*ks][2],   sacc[2*ks][3]);
                __half2 h2 = __floats2half2_rn(sacc[2*ks+1][0], sacc[2*ks+1][1]);
                __half2 h3 = __floats2half2_rn(sacc[2*ks+1][2], sacc[2*ks+1][3]);
                pa[ks][0] = *(uint32_t*)&h0; pa[ks][1] = *(uint32_t*)&h1;
                pa[ks][2] = *(uint32_t*)&h2; pa[ks][3] = *(uint32_t*)&h3;
            }

            // ---- rescale O, then O += P @ V -------------------------------
            #pragma unroll
            for (int j = 0; j < 8; j++) {
                oacc[j][0] *= al0; oacc[j][1] *= al0;
                oacc[j][2] *= al1; oacc[j][3] *= al1;
            }
            #pragma unroll
            for (int ks = 0; ks < 4; ks++) {
                #pragma unroll
                for (int ng = 0; ng < 4; ng++) {
                    uint32_t b0, b1, b2, b3;
                    uint32_t addr = vs_base +
                        ((ks * 16 + vk_row) * KS_STR + ng * 16 + vn_col) * 2;
                    ldsm_x4t(b0, b1, b2, b3, addr);
                    uint32_t bf0[2] = {b0, b1}, bf1[2] = {b2, b3};
                    mma16816h(oacc[ng * 2],     pa[ks], bf0);
                    mma16816h(oacc[ng * 2 + 1], pa[ks], bf1);
                }
            }
        }
    }

    // ---- normalize + write --------------------------------------------------
    const float il0 = 1.f / l0r;
    const float il1 = 1.f / l1r;
    float* Og = O + ((size_t)(b * SEQ + q0 + wq)) * HDIM + h * HD;
    #pragma unroll
    for (int j = 0; j < 8; j++) {
        const int col = j * 8 + t * 2;
        *(float2*)(Og + (size_t)g * HDIM + col) =
            make_float2(oacc[j][0] * il0, oacc[j][1] * il0);
        *(float2*)(Og + (size_t)(g + 8) * HDIM + col) =
            make_float2(oacc[j][2] * il1, oacc[j][3] * il1);
    }
}

// ---------------- Residual + LayerNorm ---------------------------------------
__global__ void __launch_bounds__(256) ln_kernel(
    const float* __restrict__ X, const float* __restrict__ Y,
    const float* __restrict__ g, const float* __restrict__ be,
    float* __restrict__ out)
{
    const int row = blockIdx.x;
    const int tid = threadIdx.x;
    const float* xr = X + (size_t)row * HDIM;
    const float* yr = Y + (size_t)row * HDIM;

    float4 x4 = *(const float4*)(xr + tid * 4);
    float4 y4 = *(const float4*)(yr + tid * 4);
    float v0 = x4.x + y4.x, v1 = x4.y + y4.y, v2 = x4.z + y4.z, v3 = x4.w + y4.w;

    float s  = v0 + v1 + v2 + v3;
    float ss = v0 * v0 + v1 * v1 + v2 * v2 + v3 * v3;
    #pragma unroll
    for (int off = 16; off > 0; off >>= 1) {
        s  += __shfl_xor_sync(0xffffffffu, s, off);
        ss += __shfl_xor_sync(0xffffffffu, ss, off);
    }

    __shared__ float sbuf[8], ssbuf[8];
    __shared__ float mu_s, rstd_s;
    if ((tid & 31) == 0) { sbuf[tid >> 5] = s; ssbuf[tid >> 5] = ss; }
    __syncthreads();
    if (tid == 0) {
        float S = 0.f, SS = 0.f;
        #pragma unroll
        for (int k = 0; k < 8; k++) { S += sbuf[k]; SS += ssbuf[k]; }
        float mu = S * (1.0f / HDIM);
        float var = SS * (1.0f / HDIM) - mu * mu;
        mu_s = mu;
        rstd_s = rsqrtf(var + 1e-5f);
    }
    __syncthreads();
    float mu = mu_s, rs = rstd_s;

    float4 g4 = *(const float4*)(g + tid * 4);
    float4 b4 = *(const float4*)(be + tid * 4);
    float4 o;
    o.x = (v0 - mu) * rs * g4.x + b4.x;
    o.y = (v1 - mu) * rs * g4.y + b4.y;
    o.z = (v2 - mu) * rs * g4.z + b4.z;
    o.w = (v3 - mu) * rs * g4.w + b4.w;
    *(float4*)(out + (size_t)row * HDIM + tid * 4) = o;
}

// ---------------- launch -----------------------------------------------------
extern "C" void kernel_launch(void* const* d_in, const int* in_sizes, int n_in,
                              void* d_out, int out_size)
{
    const float* query = (const float*)d_in[0];
    const float* key   = (const float*)d_in[1];
    const float* value = (const float*)d_in[2];
    const float* Wq = (const float*)d_in[4];
    const float* bq = (const float*)d_in[5];
    const float* Wk = (const float*)d_in[6];
    const float* bk = (const float*)d_in[7];
    const float* Wv = (const float*)d_in[8];
    const float* bv = (const float*)d_in[9];
    const float* Wo = (const float*)d_in[10];
    const float* bo = (const float*)d_in[11];
    const float* lg = (const float*)d_in[12];
    const float* lb = (const float*)d_in[13];
    float* out = (float*)d_out;

    __half *dQh, *dKh, *dVh;
    float *dAO, *dY;
    cudaGetSymbolAddress((void**)&dQh, g_Qh);
    cudaGetSymbolAddress((void**)&dKh, g_Kh);
    cudaGetSymbolAddress((void**)&dVh, g_Vh);
    cudaGetSymbolAddress((void**)&dAO, g_AO);
    cudaGetSymbolAddress((void**)&dY,  g_Y);

    dim3 gGemm(HDIM / 128, MROWS / 128);
    gemm_tc<__half><<<gGemm, 256>>>(query, Wq, bq, dQh, MROWS, HDIM, HDIM);
    gemm_tc<__half><<<gGemm, 256>>>(key,   Wk, bk, dKh, MROWS, HDIM, HDIM);
    gemm_tc<__half><<<gGemm, 256>>>(value, Wv, bv, dVh, MROWS, HDIM, HDIM);

    attn_fa<<<dim3(SEQ / 128, NHEAD, BATCH), 256>>>(dQh, dKh, dVh, dAO);

    gemm_tc<float><<<gGemm, 256>>>(dAO, Wo, bo, dY, MROWS, HDIM, HDIM);

    ln_kernel<<<MROWS, 256>>>(query, dY, lg, lb, out);
}

// round 5
// speedup vs baseline: 1.4258x; 1.4258x over previous
#include <cuda_runtime.h>
#include <cuda_fp16.h>
#include <cstdint>

#define BATCH 2
#define SEQ   2048
#define HDIM  1024
#define NHEAD 16
#define HD    64
#define MROWS (BATCH * SEQ)   // 4096

// ---------------- scratch (device globals: allocation-free) ------------------
__device__ __half g_Qh[MROWS * HDIM];
__device__ __half g_Kh[MROWS * HDIM];
__device__ __half g_Vh[MROWS * HDIM];
__device__ __half g_AOh[MROWS * HDIM];
__device__ float  g_Y[MROWS * HDIM];
// fp16 copies of inputs / weights
__device__ __half g_qx[MROWS * HDIM];
__device__ __half g_kx[MROWS * HDIM];
__device__ __half g_vx[MROWS * HDIM];
__device__ __half g_Wqh[HDIM * HDIM];
__device__ __half g_Wkh[HDIM * HDIM];
__device__ __half g_Wvh[HDIM * HDIM];
__device__ __half g_Woh[HDIM * HDIM];

// ---------------- helpers ----------------------------------------------------
__device__ __forceinline__ void mma16816h(float* c, const uint32_t* a, const uint32_t* b) {
    asm volatile(
        "mma.sync.aligned.m16n8k16.row.col.f32.f16.f16.f32 "
        "{%0,%1,%2,%3},{%4,%5,%6,%7},{%8,%9},{%0,%1,%2,%3};"
        : "+f"(c[0]), "+f"(c[1]), "+f"(c[2]), "+f"(c[3])
        : "r"(a[0]), "r"(a[1]), "r"(a[2]), "r"(a[3]), "r"(b[0]), "r"(b[1]));
}

__device__ __forceinline__ void ldsm_x4(uint32_t& r0, uint32_t& r1, uint32_t& r2,
                                        uint32_t& r3, uint32_t addr) {
    asm volatile("ldmatrix.sync.aligned.m8n8.x4.shared.b16 {%0,%1,%2,%3}, [%4];"
                 : "=r"(r0), "=r"(r1), "=r"(r2), "=r"(r3) : "r"(addr));
}
__device__ __forceinline__ void ldsm_x4t(uint32_t& r0, uint32_t& r1, uint32_t& r2,
                                         uint32_t& r3, uint32_t addr) {
    asm volatile("ldmatrix.sync.aligned.m8n8.x4.trans.shared.b16 {%0,%1,%2,%3}, [%4];"
                 : "=r"(r0), "=r"(r1), "=r"(r2), "=r"(r3) : "r"(addr));
}

__device__ __forceinline__ void cp16(uint32_t dst, const void* src) {
    asm volatile("cp.async.cg.shared.global [%0], [%1], 16;" :: "r"(dst), "l"(src));
}
__device__ __forceinline__ void cp_commit() {
    asm volatile("cp.async.commit_group;");
}
__device__ __forceinline__ void cp_wait0() {
    asm volatile("cp.async.wait_group 0;");
}

// ---------------- fp32 -> fp16 batched convert --------------------------------
__global__ void __launch_bounds__(256) cvt7(
    const float* s0, const float* s1, const float* s2, const float* s3,
    const float* s4, const float* s5, const float* s6,
    __half* d0, __half* d1, __half* d2, __half* d3,
    __half* d4, __half* d5, __half* d6,
    int nbig, int nsmall)
{
    const float* s;
    __half* d;
    int n;
    switch (blockIdx.y) {
        case 0: s = s0; d = d0; n = nbig; break;
        case 1: s = s1; d = d1; n = nbig; break;
        case 2: s = s2; d = d2; n = nbig; break;
        case 3: s = s3; d = d3; n = nsmall; break;
        case 4: s = s4; d = d4; n = nsmall; break;
        case 5: s = s5; d = d5; n = nsmall; break;
        default: s = s6; d = d6; n = nsmall; break;
    }
    int idx = (blockIdx.x * 256 + threadIdx.x) * 4;
    if (idx < n) {
        float4 v = *(const float4*)(s + idx);
        __half2 h0 = __floats2half2_rn(v.x, v.y);
        __half2 h1 = __floats2half2_rn(v.z, v.w);
        *(__half2*)(d + idx)     = h0;
        *(__half2*)(d + idx + 2) = h1;
    }
}

// ---------------- fp16 tensor-core GEMM: C = A[M,K] @ W[N,K]^T + bias --------
// 128x128 tile, BK=32, 256 threads (8 warps 2x4, warp tile 64x32),
// 2-stage cp.async pipeline, ldmatrix fragments.
#define GHS 40   // halves per smem row (80B, conflict-free ldsm)

template <typename OutT>
__global__ void __launch_bounds__(256, 2) gemm_f16(
    const __half* __restrict__ A, const __half* __restrict__ W,
    const float* __restrict__ bias, OutT* __restrict__ C,
    int M, int N, int K)
{
    __shared__ __half As[2][128 * GHS];
    __shared__ __half Bs[2][128 * GHS];

    const int tid  = threadIdx.x;
    const int w    = tid >> 5;
    const int lane = tid & 31;
    const int g    = lane >> 2;
    const int t    = lane & 3;
    const int wm   = (w >> 2) * 64;
    const int wn   = (w & 3) * 32;

    const int m0 = blockIdx.y * 128;
    const int n0 = blockIdx.x * 128;

    const uint32_t as_base = (uint32_t)__cvta_generic_to_shared(As);
    const uint32_t bs_base = (uint32_t)__cvta_generic_to_shared(Bs);
    const uint32_t stage_bytes = 128 * GHS * 2;

    // load mapping: 128 rows x 4 chunks of 8 halves; 512 slots, 2 per thread
    const int lr = tid >> 1;              // 0..127
    const int lc = (tid & 1) * 16;        // 0 or 16 (two chunks handled below)

    const __half* Ag = A + (size_t)(m0 + lr) * K + lc;
    const __half* Wg = W + (size_t)(n0 + lr) * K + lc;

    // fragment addresses
    const int a_row = lane & 15;
    const int a_chi = (lane >> 4) * 8;
    const int kn_row = (lane & 7) + ((lane >> 4) & 1) * 8;
    const int kn_col = ((lane >> 3) & 1) * 8;

    float acc[4][4][4];
    #pragma unroll
    for (int i = 0; i < 4; i++)
        #pragma unroll
        for (int j = 0; j < 4; j++)
            #pragma unroll
            for (int r = 0; r < 4; r++) acc[i][j][r] = 0.f;

    // preload k-block 0 into stage 0
    {
        cp16(as_base + (lr * GHS + lc) * 2,      Ag);
        cp16(as_base + (lr * GHS + lc + 8) * 2,  Ag + 8);
        cp16(bs_base + (lr * GHS + lc) * 2,      Wg);
        cp16(bs_base + (lr * GHS + lc + 8) * 2,  Wg + 8);
        cp_commit();
    }

    const int niter = K / 32;
    for (int kb = 0; kb < niter; kb++) {
        cp_wait0();
        __syncthreads();

        if (kb + 1 < niter) {
            const uint32_t st = ((kb + 1) & 1) * stage_bytes;
            const __half* Ag2 = Ag + (size_t)(kb + 1) * 32;
            const __half* Wg2 = Wg + (size_t)(kb + 1) * 32;
            cp16(as_base + st + (lr * GHS + lc) * 2,     Ag2);
            cp16(as_base + st + (lr * GHS + lc + 8) * 2, Ag2 + 8);
            cp16(bs_base + st + (lr * GHS + lc) * 2,     Wg2);
            cp16(bs_base + st + (lr * GHS + lc + 8) * 2, Wg2 + 8);
            cp_commit();
        }

        const uint32_t sa = as_base + (kb & 1) * stage_bytes;
        const uint32_t sb = bs_base + (kb & 1) * stage_bytes;

        #pragma unroll
        for (int ks = 0; ks < 2; ks++) {
            const int k0 = ks * 16;
            uint32_t af[4][4];
            #pragma unroll
            for (int mt = 0; mt < 4; mt++) {
                uint32_t addr = sa + ((wm + mt * 16 + a_row) * GHS + k0 + a_chi) * 2;
                ldsm_x4(af[mt][0], af[mt][1], af[mt][2], af[mt][3], addr);
            }
            uint32_t bfr[2][4];
            #pragma unroll
            for (int ng = 0; ng < 2; ng++) {
                uint32_t addr = sb + ((wn + ng * 16 + kn_row) * GHS + k0 + kn_col) * 2;
                ldsm_x4(bfr[ng][0], bfr[ng][1], bfr[ng][2], bfr[ng][3], addr);
            }
            #pragma unroll
            for (int mt = 0; mt < 4; mt++)
                #pragma unroll
                for (int nt = 0; nt < 4; nt++) {
                    uint32_t bf[2] = {bfr[nt >> 1][(nt & 1) * 2],
                                      bfr[nt >> 1][(nt & 1) * 2 + 1]};
                    mma16816h(acc[mt][nt], af[mt], bf);
                }
        }
    }

    #pragma unroll
    for (int mt = 0; mt < 4; mt++) {
        const int row0 = m0 + wm + mt * 16 + g;
        const int row1 = row0 + 8;
        #pragma unroll
        for (int nt = 0; nt < 4; nt++) {
            const int col = n0 + wn + nt * 8 + t * 2;
            const float b0 = bias[col], b1 = bias[col + 1];
            float c00 = acc[mt][nt][0] + b0, c01 = acc[mt][nt][1] + b1;
            float c10 = acc[mt][nt][2] + b0, c11 = acc[mt][nt][3] + b1;
            if constexpr (sizeof(OutT) == 4) {
                *(float2*)((float*)C + (size_t)row0 * N + col) = make_float2(c00, c01);
                *(float2*)((float*)C + (size_t)row1 * N + col) = make_float2(c10, c11);
            } else {
                *(__half2*)((__half*)C + (size_t)row0 * N + col) = __floats2half2_rn(c00, c01);
                *(__half2*)((__half*)C + (size_t)row1 * N + col) = __floats2half2_rn(c10, c11);
            }
        }
    }
}

// ---------------- FA2-style fp16 flash attention (causal) --------------------
// 128 q-rows/block (8 warps x 16), K-tile 64, 2-stage cp.async pipeline.
#define KS_STR 72

__global__ void __launch_bounds__(256) attn_fa(
    const __half* __restrict__ Qh, const __half* __restrict__ Kh,
    const __half* __restrict__ Vh, __half* __restrict__ O)
{
    __shared__ __half Ks[2][64 * KS_STR];
    __shared__ __half Vs[2][64 * KS_STR];

    const int tid  = threadIdx.x;
    const int w    = tid >> 5;
    const int lane = tid & 31;
    const int g    = lane >> 2;
    const int t    = lane & 3;
    const int wq   = w * 16;

    const int q0 = (gridDim.x - 1 - blockIdx.x) * 128;
    const int h  = blockIdx.y;
    const int b  = blockIdx.z;

    const uint32_t ks_base = (uint32_t)__cvta_generic_to_shared(Ks);
    const uint32_t vs_base = (uint32_t)__cvta_generic_to_shared(Vs);
    const uint32_t stage_b = 64 * KS_STR * 2;

    // ---- stage Q tile [128][64] into the Ks[0..1] region --------------------
    const __half* Qg = Qh + ((size_t)(b * SEQ + q0)) * HDIM + h * HD;
    #pragma unroll
    for (int j = 0; j < 4; j++) {
        int i = tid + j * 256;
        int r = i >> 3;
        int c8 = (i & 7) * 8;
        cp16(ks_base + (r * KS_STR + c8) * 2, Qg + (size_t)r * HDIM + c8);
    }
    cp_commit();
    cp_wait0();
    __syncthreads();

    uint32_t qf[4][4];   // scaled by (1/8)*log2(e) -> exp2 softmax
    {
        const __half2 sc = __half2half2(__float2half(0.125f * 1.44269504f));
        const int row = wq + (lane & 15);
        const int chi = (lane >> 4) * 8;
        #pragma unroll
        for (int ks = 0; ks < 4; ks++) {
            uint32_t addr = ks_base + (row * KS_STR + ks * 16 + chi) * 2;
            ldsm_x4(qf[ks][0], qf[ks][1], qf[ks][2], qf[ks][3], addr);
            #pragma unroll
            for (int r = 0; r < 4; r++) {
                __half2 v = *(__half2*)&qf[ks][r];
                v = __hmul2(v, sc);
                qf[ks][r] = *(uint32_t*)&v;
            }
        }
    }
    __syncthreads();

    float m0r = -1e30f, m1r = -1e30f, l0r = 0.f, l1r = 0.f;
    float oacc[8][4];
    #pragma unroll
    for (int j = 0; j < 8; j++)
        #pragma unroll
        for (int r = 0; r < 4; r++) oacc[j][r] = 0.f;

    const int kn_row = (lane & 7) + ((lane >> 4) & 1) * 8;
    const int kn_col = ((lane >> 3) & 1) * 8;
    const int vk_row = (lane & 7) + ((lane >> 3) & 1) * 8;
    const int vn_col = (lane >> 4) * 8;

    const int jmax = (q0 + 127) / 64;

    // preload tile 0 into stage 0
    {
        const __half* Kg = Kh + ((size_t)(b * SEQ)) * HDIM + h * HD;
        const __half* Vg = Vh + ((size_t)(b * SEQ)) * HDIM + h * HD;
        #pragma unroll
        for (int j = 0; j < 2; j++) {
            int i = tid + j * 256;
            int r = i >> 3;
            int c8 = (i & 7) * 8;
            cp16(ks_base + (r * KS_STR + c8) * 2, Kg + (size_t)r * HDIM + c8);
            cp16(vs_base + (r * KS_STR + c8) * 2, Vg + (size_t)r * HDIM + c8);
        }
        cp_commit();
    }

    for (int jt = 0; jt <= jmax; jt++) {
        const int k0g = jt * 64;

        cp_wait0();
        __syncthreads();

        if (jt + 1 <= jmax) {
            const uint32_t st = ((jt + 1) & 1) * stage_b;
            const __half* Kg = Kh + ((size_t)(b * SEQ + (jt + 1) * 64)) * HDIM + h * HD;
            const __half* Vg = Vh + ((size_t)(b * SEQ + (jt + 1) * 64)) * HDIM + h * HD;
            #pragma unroll
            for (int j = 0; j < 2; j++) {
                int i = tid + j * 256;
                int r = i >> 3;
                int c8 = (i & 7) * 8;
                cp16(ks_base + st + (r * KS_STR + c8) * 2, Kg + (size_t)r * HDIM + c8);
                cp16(vs_base + st + (r * KS_STR + c8) * 2, Vg + (size_t)r * HDIM + c8);
            }
            cp_commit();
        }

        const uint32_t sk = ks_base + (jt & 1) * stage_b;
        const uint32_t sv = vs_base + (jt & 1) * stage_b;

        const bool active = (k0g <= q0 + wq + 15);
        if (active) {
            float sacc[8][4];
            #pragma unroll
            for (int j = 0; j < 8; j++)
                #pragma unroll
                for (int r = 0; r < 4; r++) sacc[j][r] = 0.f;

            #pragma unroll
            for (int ks = 0; ks < 4; ks++) {
                #pragma unroll
                for (int ng = 0; ng < 4; ng++) {
                    uint32_t b0, b1, b2, b3;
                    uint32_t addr = sk + ((ng * 16 + kn_row) * KS_STR + ks * 16 + kn_col) * 2;
                    ldsm_x4(b0, b1, b2, b3, addr);
                    uint32_t bf0[2] = {b0, b1}, bf1[2] = {b2, b3};
                    mma16816h(sacc[ng * 2],     qf[ks], bf0);
                    mma16816h(sacc[ng * 2 + 1], qf[ks], bf1);
                }
            }

            if (k0g + 63 > q0 + wq) {
                const int row0 = q0 + wq + g;
                const int row1 = row0 + 8;
                #pragma unroll
                for (int j = 0; j < 8; j++) {
                    const int col = k0g + j * 8 + t * 2;
                    if (col > row0)     sacc[j][0] = -1e30f;
                    if (col + 1 > row0) sacc[j][1] = -1e30f;
                    if (col > row1)     sacc[j][2] = -1e30f;
                    if (col + 1 > row1) sacc[j][3] = -1e30f;
                }
            }

            float tm0 = -1e30f, tm1 = -1e30f;
            #pragma unroll
            for (int j = 0; j < 8; j++) {
                tm0 = fmaxf(tm0, fmaxf(sacc[j][0], sacc[j][1]));
                tm1 = fmaxf(tm1, fmaxf(sacc[j][2], sacc[j][3]));
            }
            tm0 = fmaxf(tm0, __shfl_xor_sync(0xffffffffu, tm0, 1));
            tm0 = fmaxf(tm0, __shfl_xor_sync(0xffffffffu, tm0, 2));
            tm1 = fmaxf(tm1, __shfl_xor_sync(0xffffffffu, tm1, 1));
            tm1 = fmaxf(tm1, __shfl_xor_sync(0xffffffffu, tm1, 2));

            const float mn0 = fmaxf(m0r, tm0);
            const float mn1 = fmaxf(m1r, tm1);
            const float al0 = exp2f(m0r - mn0);
            const float al1 = exp2f(m1r - mn1);
            m0r = mn0; m1r = mn1;

            float rs0 = 0.f, rs1 = 0.f;
            #pragma unroll
            for (int j = 0; j < 8; j++) {
                sacc[j][0] = exp2f(sacc[j][0] - mn0);
                sacc[j][1] = exp2f(sacc[j][1] - mn0);
                sacc[j][2] = exp2f(sacc[j][2] - mn1);
                sacc[j][3] = exp2f(sacc[j][3] - mn1);
                rs0 += sacc[j][0] + sacc[j][1];
                rs1 += sacc[j][2] + sacc[j][3];
            }
            rs0 += __shfl_xor_sync(0xffffffffu, rs0, 1);
            rs0 += __shfl_xor_sync(0xffffffffu, rs0, 2);
            rs1 += __shfl_xor_sync(0xffffffffu, rs1, 1);
            rs1 += __shfl_xor_sync(0xffffffffu, rs1, 2);
            l0r = l0r * al0 + rs0;
            l1r = l1r * al1 + rs1;

            uint32_t pa[4][4];
            #pragma unroll
            for (int ks = 0; ks < 4; ks++) {
                __half2 h0 = __floats2half2_rn(sacc[2*ks][0],   sacc[2*ks][1]);
                __half2 h1 = __floats2half2_rn(sacc[2*ks][2],   sacc[2*ks][3]);
                __half2 h2 = __floats2half2_rn(sacc[2*ks+1][0], sacc[2*ks+1][1]);
                __half2 h3 = __floats2half2_rn(sacc[2*ks+1][2], sacc[2*ks+1][3]);
                pa[ks][0] = *(uint32_t*)&h0; pa[ks][1] = *(uint32_t*)&h1;
                pa[ks][2] = *(uint32_t*)&h2; pa[ks][3] = *(uint32_t*)&h3;
            }

            #pragma unroll
            for (int j = 0; j < 8; j++) {
                oacc[j][0] *= al0; oacc[j][1] *= al0;
                oacc[j][2] *= al1; oacc[j][3] *= al1;
            }
            #pragma unroll
            for (int ks = 0; ks < 4; ks++) {
                #pragma unroll
                for (int ng = 0; ng < 4; ng++) {
                    uint32_t b0, b1, b2, b3;
                    uint32_t addr = sv + ((ks * 16 + vk_row) * KS_STR + ng * 16 + vn_col) * 2;
                    ldsm_x4t(b0, b1, b2, b3, addr);
                    uint32_t bf0[2] = {b0, b1}, bf1[2] = {b2, b3};
                    mma16816h(oacc[ng * 2],     pa[ks], bf0);
                    mma16816h(oacc[ng * 2 + 1], pa[ks], bf1);
                }
            }
        }
    }

    const float il0 = 1.f / l0r;
    const float il1 = 1.f / l1r;
    __half* Og = O + ((size_t)(b * SEQ + q0 + wq)) * HDIM + h * HD;
    #pragma unroll
    for (int j = 0; j < 8; j++) {
        const int col = j * 8 + t * 2;
        *(__half2*)(Og + (size_t)g * HDIM + col) =
            __floats2half2_rn(oacc[j][0] * il0, oacc[j][1] * il0);
        *(__half2*)(Og + (size_t)(g + 8) * HDIM + col) =
            __floats2half2_rn(oacc[j][2] * il1, oacc[j][3] * il1);
    }
}

// ---------------- Residual + LayerNorm ---------------------------------------
__global__ void __launch_bounds__(256) ln_kernel(
    const float* __restrict__ X, const float* __restrict__ Y,
    const float* __restrict__ g, const float* __restrict__ be,
    float* __restrict__ out)
{
    const int row = blockIdx.x;
    const int tid = threadIdx.x;
    const float* xr = X + (size_t)row * HDIM;
    const float* yr = Y + (size_t)row * HDIM;

    float4 x4 = *(const float4*)(xr + tid * 4);
    float4 y4 = *(const float4*)(yr + tid * 4);
    float v0 = x4.x + y4.x, v1 = x4.y + y4.y, v2 = x4.z + y4.z, v3 = x4.w + y4.w;

    float s  = v0 + v1 + v2 + v3;
    float ss = v0 * v0 + v1 * v1 + v2 * v2 + v3 * v3;
    #pragma unroll
    for (int off = 16; off > 0; off >>= 1) {
        s  += __shfl_xor_sync(0xffffffffu, s, off);
        ss += __shfl_xor_sync(0xffffffffu, ss, off);
    }

    __shared__ float sbuf[8], ssbuf[8];
    __shared__ float mu_s, rstd_s;
    if ((tid & 31) == 0) { sbuf[tid >> 5] = s; ssbuf[tid >> 5] = ss; }
    __syncthreads();
    if (tid == 0) {
        float S = 0.f, SS = 0.f;
        #pragma unroll
        for (int k = 0; k < 8; k++) { S += sbuf[k]; SS += ssbuf[k]; }
        float mu = S * (1.0f / HDIM);
        float var = SS * (1.0f / HDIM) - mu * mu;
        mu_s = mu;
        rstd_s = rsqrtf(var + 1e-5f);
    }
    __syncthreads();
    float mu = mu_s, rs = rstd_s;

    float4 g4 = *(const float4*)(g + tid * 4);
    float4 b4 = *(const float4*)(be + tid * 4);
    float4 o;
    o.x = (v0 - mu) * rs * g4.x + b4.x;
    o.y = (v1 - mu) * rs * g4.y + b4.y;
    o.z = (v2 - mu) * rs * g4.z + b4.z;
    o.w = (v3 - mu) * rs * g4.w + b4.w;
    *(float4*)(out + (size_t)row * HDIM + tid * 4) = o;
}

// ---------------- launch -----------------------------------------------------
extern "C" void kernel_launch(void* const* d_in, const int* in_sizes, int n_in,
                              void* d_out, int out_size)
{
    const float* query = (const float*)d_in[0];
    const float* key   = (const float*)d_in[1];
    const float* value = (const float*)d_in[2];
    const float* Wq = (const float*)d_in[4];
    const float* bq = (const float*)d_in[5];
    const float* Wk = (const float*)d_in[6];
    const float* bk = (const float*)d_in[7];
    const float* Wv = (const float*)d_in[8];
    const float* bv = (const float*)d_in[9];
    const float* Wo = (const float*)d_in[10];
    const float* bo = (const float*)d_in[11];
    const float* lg = (const float*)d_in[12];
    const float* lb = (const float*)d_in[13];
    float* out = (float*)d_out;

    __half *dQh, *dKh, *dVh, *dAOh, *dqx, *dkx, *dvx, *dWq, *dWk, *dWv, *dWo;
    float *dY;
    cudaGetSymbolAddress((void**)&dQh, g_Qh);
    cudaGetSymbolAddress((void**)&dKh, g_Kh);
    cudaGetSymbolAddress((void**)&dVh, g_Vh);
    cudaGetSymbolAddress((void**)&dAOh, g_AOh);
    cudaGetSymbolAddress((void**)&dY,  g_Y);
    cudaGetSymbolAddress((void**)&dqx, g_qx);
    cudaGetSymbolAddress((void**)&dkx, g_kx);
    cudaGetSymbolAddress((void**)&dvx, g_vx);
    cudaGetSymbolAddress((void**)&dWq, g_Wqh);
    cudaGetSymbolAddress((void**)&dWk, g_Wkh);
    cudaGetSymbolAddress((void**)&dWv, g_Wvh);
    cudaGetSymbolAddress((void**)&dWo, g_Woh);

    const int nbig = MROWS * HDIM;        // 4M
    const int nsmall = HDIM * HDIM;       // 1M
    dim3 gCvt(nbig / (256 * 4), 7);
    cvt7<<<gCvt, 256>>>(query, key, value, Wq, Wk, Wv, Wo,
                        dqx, dkx, dvx, dWq, dWk, dWv, dWo, nbig, nsmall);

    dim3 gGemm(HDIM / 128, MROWS / 128);
    gemm_f16<__half><<<gGemm, 256>>>(dqx, dWq, bq, dQh, MROWS, HDIM, HDIM);
    gemm_f16<__half><<<gGemm, 256>>>(dkx, dWk, bk, dKh, MROWS, HDIM, HDIM);
    gemm_f16<__half><<<gGemm, 256>>>(dvx, dWv, bv, dVh, MROWS, HDIM, HDIM);

    attn_fa<<<dim3(SEQ / 128, NHEAD, BATCH), 256>>>(dQh, dKh, dVh, dAOh);

    gemm_f16<float><<<gGemm, 256>>>(dAOh, dWo, bo, dY, MROWS, HDIM, HDIM);

    ln_kernel<<<MROWS, 256>>>(query, dY, lg, lb, out);
}

// round 6
// speedup vs baseline: 1.4711x; 1.0318x over previous
#include <cuda_runtime.h>
#include <cuda_fp16.h>
#include <cstdint>

#define BATCH 2
#define SEQ   2048
#define HDIM  1024
#define NHEAD 16
#define HD    64
#define MROWS (BATCH * SEQ)   // 4096

// ---------------- scratch (device globals: allocation-free) ------------------
__device__ __half g_Qh[MROWS * HDIM];
__device__ __half g_Kh[MROWS * HDIM];
__device__ __half g_Vh[MROWS * HDIM];
__device__ __half g_AOh[MROWS * HDIM];
__device__ float  g_Y[MROWS * HDIM];
__device__ __half g_qx[MROWS * HDIM];
__device__ __half g_kx[MROWS * HDIM];
__device__ __half g_vx[MROWS * HDIM];
__device__ __half g_Wqh[HDIM * HDIM];
__device__ __half g_Wkh[HDIM * HDIM];
__device__ __half g_Wvh[HDIM * HDIM];
__device__ __half g_Woh[HDIM * HDIM];

// ---------------- helpers ----------------------------------------------------
__device__ __forceinline__ void mma16816h(float* c, const uint32_t* a, const uint32_t* b) {
    asm volatile(
        "mma.sync.aligned.m16n8k16.row.col.f32.f16.f16.f32 "
        "{%0,%1,%2,%3},{%4,%5,%6,%7},{%8,%9},{%0,%1,%2,%3};"
        : "+f"(c[0]), "+f"(c[1]), "+f"(c[2]), "+f"(c[3])
        : "r"(a[0]), "r"(a[1]), "r"(a[2]), "r"(a[3]), "r"(b[0]), "r"(b[1]));
}

__device__ __forceinline__ void ldsm_x4(uint32_t& r0, uint32_t& r1, uint32_t& r2,
                                        uint32_t& r3, uint32_t addr) {
    asm volatile("ldmatrix.sync.aligned.m8n8.x4.shared.b16 {%0,%1,%2,%3}, [%4];"
                 : "=r"(r0), "=r"(r1), "=r"(r2), "=r"(r3) : "r"(addr));
}
__device__ __forceinline__ void ldsm_x4t(uint32_t& r0, uint32_t& r1, uint32_t& r2,
                                         uint32_t& r3, uint32_t addr) {
    asm volatile("ldmatrix.sync.aligned.m8n8.x4.trans.shared.b16 {%0,%1,%2,%3}, [%4];"
                 : "=r"(r0), "=r"(r1), "=r"(r2), "=r"(r3) : "r"(addr));
}

__device__ __forceinline__ void cp16(uint32_t dst, const void* src) {
    asm volatile("cp.async.cg.shared.global [%0], [%1], 16;" :: "r"(dst), "l"(src));
}
__device__ __forceinline__ void cp_commit() {
    asm volatile("cp.async.commit_group;");
}
template <int N>
__device__ __forceinline__ void cp_wait() {
    asm volatile("cp.async.wait_group %0;" :: "n"(N));
}

// ---------------- fp32 -> fp16 batched convert --------------------------------
__global__ void __launch_bounds__(256) cvt7(
    const float* s0, const float* s1, const float* s2, const float* s3,
    const float* s4, const float* s5, const float* s6,
    __half* d0, __half* d1, __half* d2, __half* d3,
    __half* d4, __half* d5, __half* d6,
    int nbig, int nsmall)
{
    const float* s;
    __half* d;
    int n;
    switch (blockIdx.y) {
        case 0: s = s0; d = d0; n = nbig; break;
        case 1: s = s1; d = d1; n = nbig; break;
        case 2: s = s2; d = d2; n = nbig; break;
        case 3: s = s3; d = d3; n = nsmall; break;
        case 4: s = s4; d = d4; n = nsmall; break;
        case 5: s = s5; d = d5; n = nsmall; break;
        default: s = s6; d = d6; n = nsmall; break;
    }
    int idx = (blockIdx.x * 256 + threadIdx.x) * 4;
    if (idx < n) {
        float4 v = *(const float4*)(s + idx);
        *(__half2*)(d + idx)     = __floats2half2_rn(v.x, v.y);
        *(__half2*)(d + idx + 2) = __floats2half2_rn(v.z, v.w);
    }
}

// ---------------- fp16 GEMM core: C = A[M,K] @ W[N,K]^T + bias ---------------
// 128x128 tile, BK=32, 3-stage cp.async pipeline, 8 warps (warp tile 64x32).
#define GHS 40                        // halves per smem row (80 B)
#define G_STAGE (128 * GHS)           // halves per (A or B) stage
#define G_SMEM_HALVES (3 * 2 * G_STAGE)

template <typename OutT>
__device__ __forceinline__ void gemm_core(
    const __half* __restrict__ A, const __half* __restrict__ W,
    const float* __restrict__ bias, OutT* __restrict__ C,
    int M, int N, int K, __half* smem, int m0, int n0)
{
    const int tid  = threadIdx.x;
    const int w    = tid >> 5;
    const int lane = tid & 31;
    const int g    = lane >> 2;
    const int t    = lane & 3;
    const int wm   = (w >> 2) * 64;
    const int wn   = (w & 3) * 32;

    const uint32_t s_base = (uint32_t)__cvta_generic_to_shared(smem);
    const uint32_t stage_bytes = G_STAGE * 2;      // per A-or-B stage
    // layout: [A0 B0 A1 B1 A2 B2], each G_STAGE halves

    const int lr = tid >> 1;
    const int lc = (tid & 1) * 16;

    const __half* Ag = A + (size_t)(m0 + lr) * K + lc;
    const __half* Wg = W + (size_t)(n0 + lr) * K + lc;

    const int a_row = lane & 15;
    const int a_chi = (lane >> 4) * 8;
    const int kn_row = (lane & 7) + ((lane >> 4) & 1) * 8;
    const int kn_col = ((lane >> 3) & 1) * 8;

    float acc[4][4][4];
    #pragma unroll
    for (int i = 0; i < 4; i++)
        #pragma unroll
        for (int j = 0; j < 4; j++)
            #pragma unroll
            for (int r = 0; r < 4; r++) acc[i][j][r] = 0.f;

    const int niter = K / 32;

    // prologue: stages 0,1
    #pragma unroll
    for (int s = 0; s < 2; s++) {
        const __half* Ag2 = Ag + (size_t)s * 32;
        const __half* Wg2 = Wg + (size_t)s * 32;
        uint32_t sa = s_base + (2 * s) * stage_bytes;
        uint32_t sb = s_base + (2 * s + 1) * stage_bytes;
        cp16(sa + (lr * GHS + lc) * 2,     Ag2);
        cp16(sa + (lr * GHS + lc + 8) * 2, Ag2 + 8);
        cp16(sb + (lr * GHS + lc) * 2,     Wg2);
        cp16(sb + (lr * GHS + lc + 8) * 2, Wg2 + 8);
        cp_commit();
    }

    for (int kb = 0; kb < niter; kb++) {
        cp_wait<1>();
        __syncthreads();

        if (kb + 2 < niter) {
            const int s = (kb + 2) % 3;
            const __half* Ag2 = Ag + (size_t)(kb + 2) * 32;
            const __half* Wg2 = Wg + (size_t)(kb + 2) * 32;
            uint32_t sa = s_base + (2 * s) * stage_bytes;
            uint32_t sb = s_base + (2 * s + 1) * stage_bytes;
            cp16(sa + (lr * GHS + lc) * 2,     Ag2);
            cp16(sa + (lr * GHS + lc + 8) * 2, Ag2 + 8);
            cp16(sb + (lr * GHS + lc) * 2,     Wg2);
            cp16(sb + (lr * GHS + lc + 8) * 2, Wg2 + 8);
        }
        cp_commit();

        const int cs = kb % 3;
        const uint32_t sa = s_base + (2 * cs) * stage_bytes;
        const uint32_t sb = s_base + (2 * cs + 1) * stage_bytes;

        #pragma unroll
        for (int ks = 0; ks < 2; ks++) {
            const int k0 = ks * 16;
            uint32_t af[4][4];
            #pragma unroll
            for (int mt = 0; mt < 4; mt++) {
                uint32_t addr = sa + ((wm + mt * 16 + a_row) * GHS + k0 + a_chi) * 2;
                ldsm_x4(af[mt][0], af[mt][1], af[mt][2], af[mt][3], addr);
            }
            uint32_t bfr[2][4];
            #pragma unroll
            for (int ng = 0; ng < 2; ng++) {
                uint32_t addr = sb + ((wn + ng * 16 + kn_row) * GHS + k0 + kn_col) * 2;
                ldsm_x4(bfr[ng][0], bfr[ng][1], bfr[ng][2], bfr[ng][3], addr);
            }
            #pragma unroll
            for (int mt = 0; mt < 4; mt++)
                #pragma unroll
                for (int nt = 0; nt < 4; nt++) {
                    uint32_t bf[2] = {bfr[nt >> 1][(nt & 1) * 2],
                                      bfr[nt >> 1][(nt & 1) * 2 + 1]};
                    mma16816h(acc[mt][nt], af[mt], bf);
                }
        }
    }

    #pragma unroll
    for (int mt = 0; mt < 4; mt++) {
        const int row0 = m0 + wm + mt * 16 + g;
        const int row1 = row0 + 8;
        #pragma unroll
        for (int nt = 0; nt < 4; nt++) {
            const int col = n0 + wn + nt * 8 + t * 2;
            const float b0 = bias[col], b1 = bias[col + 1];
            float c00 = acc[mt][nt][0] + b0, c01 = acc[mt][nt][1] + b1;
            float c10 = acc[mt][nt][2] + b0, c11 = acc[mt][nt][3] + b1;
            if constexpr (sizeof(OutT) == 4) {
                *(float2*)((float*)C + (size_t)row0 * N + col) = make_float2(c00, c01);
                *(float2*)((float*)C + (size_t)row1 * N + col) = make_float2(c10, c11);
            } else {
                *(__half2*)((__half*)C + (size_t)row0 * N + col) = __floats2half2_rn(c00, c01);
                *(__half2*)((__half*)C + (size_t)row1 * N + col) = __floats2half2_rn(c10, c11);
            }
        }
    }
}

// Fused QKV projection: blockIdx.z selects (A, W, bias, C)
__global__ void __launch_bounds__(256, 2) gemm_qkv(
    const __half* Aq, const __half* Ak, const __half* Av,
    const __half* Wq, const __half* Wk, const __half* Wv,
    const float* bq, const float* bk, const float* bv,
    __half* Cq, __half* Ck, __half* Cv)
{
    extern __shared__ __half gsm[];
    const int z = blockIdx.z;
    const __half* A = (z == 0) ? Aq : (z == 1) ? Ak : Av;
    const __half* W = (z == 0) ? Wq : (z == 1) ? Wk : Wv;
    const float*  b = (z == 0) ? bq : (z == 1) ? bk : bv;
    __half*       C = (z == 0) ? Cq : (z == 1) ? Ck : Cv;
    gemm_core<__half>(A, W, b, C, MROWS, HDIM, HDIM, gsm,
                      blockIdx.y * 128, blockIdx.x * 128);
}

__global__ void __launch_bounds__(256, 2) gemm_o(
    const __half* A, const __half* W, const float* bias, float* C)
{
    extern __shared__ __half gsm[];
    gemm_core<float>(A, W, bias, C, MROWS, HDIM, HDIM, gsm,
                     blockIdx.y * 128, blockIdx.x * 128);
}

// ---------------- FA2-style fp16 flash attention (causal) --------------------
// 128 q-rows/block (8 warps x 16), K-tile 64, 3-stage cp.async pipeline.
#define KS_STR 72
#define A_STAGE (64 * KS_STR)                 // halves per (K or V) stage
#define A_SMEM_HALVES (3 * 2 * A_STAGE)

__global__ void __launch_bounds__(256) attn_fa(
    const __half* __restrict__ Qh, const __half* __restrict__ Kh,
    const __half* __restrict__ Vh, __half* __restrict__ O)
{
    extern __shared__ __half asm_[];
    __half* Ks = asm_;                         // 3 stages
    __half* Vs = asm_ + 3 * A_STAGE;           // 3 stages

    const int tid  = threadIdx.x;
    const int w    = tid >> 5;
    const int lane = tid & 31;
    const int g    = lane >> 2;
    const int t    = lane & 3;
    const int wq   = w * 16;

    const int q0 = (gridDim.x - 1 - blockIdx.x) * 128;
    const int h  = blockIdx.y;
    const int b  = blockIdx.z;

    const uint32_t ks_base = (uint32_t)__cvta_generic_to_shared(Ks);
    const uint32_t vs_base = (uint32_t)__cvta_generic_to_shared(Vs);
    const uint32_t stage_b = A_STAGE * 2;

    // ---- stage Q tile [128][64] into Ks stages 0-1 --------------------------
    const __half* Qg = Qh + ((size_t)(b * SEQ + q0)) * HDIM + h * HD;
    #pragma unroll
    for (int j = 0; j < 4; j++) {
        int i = tid + j * 256;
        int r = i >> 3;
        int c8 = (i & 7) * 8;
        cp16(ks_base + (r * KS_STR + c8) * 2, Qg + (size_t)r * HDIM + c8);
    }
    cp_commit();
    cp_wait<0>();
    __syncthreads();

    uint32_t qf[4][4];   // scaled by (1/8)*log2(e)
    {
        const __half2 sc = __half2half2(__float2half(0.125f * 1.44269504f));
        const int row = wq + (lane & 15);
        const int chi = (lane >> 4) * 8;
        #pragma unroll
        for (int ks = 0; ks < 4; ks++) {
            uint32_t addr = ks_base + (row * KS_STR + ks * 16 + chi) * 2;
            ldsm_x4(qf[ks][0], qf[ks][1], qf[ks][2], qf[ks][3], addr);
            #pragma unroll
            for (int r = 0; r < 4; r++) {
                __half2 v = *(__half2*)&qf[ks][r];
                v = __hmul2(v, sc);
                qf[ks][r] = *(uint32_t*)&v;
            }
        }
    }
    __syncthreads();

    float m0r = -1e30f, m1r = -1e30f, l0r = 0.f, l1r = 0.f;
    float oacc[8][4];
    #pragma unroll
    for (int j = 0; j < 8; j++)
        #pragma unroll
        for (int r = 0; r < 4; r++) oacc[j][r] = 0.f;

    const int kn_row = (lane & 7) + ((lane >> 4) & 1) * 8;
    const int kn_col = ((lane >> 3) & 1) * 8;
    const int vk_row = (lane & 7) + ((lane >> 3) & 1) * 8;
    const int vn_col = (lane >> 4) * 8;

    const int jmax = (q0 + 127) / 64;

    // prologue: tiles 0,1 (empty commit keeps group arithmetic uniform)
    #pragma unroll
    for (int p = 0; p < 2; p++) {
        if (p <= jmax) {
            const uint32_t st = p * stage_b;
            const __half* Kg = Kh + ((size_t)(b * SEQ + p * 64)) * HDIM + h * HD;
            const __half* Vg = Vh + ((size_t)(b * SEQ + p * 64)) * HDIM + h * HD;
            #pragma unroll
            for (int j = 0; j < 2; j++) {
                int i = tid + j * 256;
                int r = i >> 3;
                int c8 = (i & 7) * 8;
                cp16(ks_base + st + (r * KS_STR + c8) * 2, Kg + (size_t)r * HDIM + c8);
                cp16(vs_base + st + (r * KS_STR + c8) * 2, Vg + (size_t)r * HDIM + c8);
            }
        }
        cp_commit();
    }

    for (int jt = 0; jt <= jmax; jt++) {
        const int k0g = jt * 64;

        cp_wait<1>();
        __syncthreads();

        if (jt + 2 <= jmax) {
            const int s = (jt + 2) % 3;
            const uint32_t st = s * stage_b;
            const __half* Kg = Kh + ((size_t)(b * SEQ + (jt + 2) * 64)) * HDIM + h * HD;
            const __half* Vg = Vh + ((size_t)(b * SEQ + (jt + 2) * 64)) * HDIM + h * HD;
            #pragma unroll
            for (int j = 0; j < 2; j++) {
                int i = tid + j * 256;
                int r = i >> 3;
                int c8 = (i & 7) * 8;
                cp16(ks_base + st + (r * KS_STR + c8) * 2, Kg + (size_t)r * HDIM + c8);
                cp16(vs_base + st + (r * KS_STR + c8) * 2, Vg + (size_t)r * HDIM + c8);
            }
        }
        cp_commit();

        const uint32_t sk = ks_base + (jt % 3) * stage_b;
        const uint32_t sv = vs_base + (jt % 3) * stage_b;

        const bool active = (k0g <= q0 + wq + 15);
        if (active) {
            float sacc[8][4];
            #pragma unroll
            for (int j = 0; j < 8; j++)
                #pragma unroll
                for (int r = 0; r < 4; r++) sacc[j][r] = 0.f;

            #pragma unroll
            for (int ks = 0; ks < 4; ks++) {
                #pragma unroll
                for (int ng = 0; ng < 4; ng++) {
                    uint32_t b0, b1, b2, b3;
                    uint32_t addr = sk + ((ng * 16 + kn_row) * KS_STR + ks * 16 + kn_col) * 2;
                    ldsm_x4(b0, b1, b2, b3, addr);
                    uint32_t bf0[2] = {b0, b1}, bf1[2] = {b2, b3};
                    mma16816h(sacc[ng * 2],     qf[ks], bf0);
                    mma16816h(sacc[ng * 2 + 1], qf[ks], bf1);
                }
            }

            if (k0g + 63 > q0 + wq) {
                const int row0 = q0 + wq + g;
                const int row1 = row0 + 8;
                #pragma unroll
                for (int j = 0; j < 8; j++) {
                    const int col = k0g + j * 8 + t * 2;
                    if (col > row0)     sacc[j][0] = -1e30f;
                    if (col + 1 > row0) sacc[j][1] = -1e30f;
                    if (col > row1)     sacc[j][2] = -1e30f;
                    if (col + 1 > row1) sacc[j][3] = -1e30f;
                }
            }

            float tm0 = -1e30f, tm1 = -1e30f;
            #pragma unroll
            for (int j = 0; j < 8; j++) {
                tm0 = fmaxf(tm0, fmaxf(sacc[j][0], sacc[j][1]));
                tm1 = fmaxf(tm1, fmaxf(sacc[j][2], sacc[j][3]));
            }
            tm0 = fmaxf(tm0, __shfl_xor_sync(0xffffffffu, tm0, 1));
            tm0 = fmaxf(tm0, __shfl_xor_sync(0xffffffffu, tm0, 2));
            tm1 = fmaxf(tm1, __shfl_xor_sync(0xffffffffu, tm1, 1));
            tm1 = fmaxf(tm1, __shfl_xor_sync(0xffffffffu, tm1, 2));

            const float mn0 = fmaxf(m0r, tm0);
            const float mn1 = fmaxf(m1r, tm1);
            const float al0 = exp2f(m0r - mn0);
            const float al1 = exp2f(m1r - mn1);
            m0r = mn0; m1r = mn1;

            float rs0 = 0.f, rs1 = 0.f;
            #pragma unroll
            for (int j = 0; j < 8; j++) {
                sacc[j][0] = exp2f(sacc[j][0] - mn0);
                sacc[j][1] = exp2f(sacc[j][1] - mn0);
                sacc[j][2] = exp2f(sacc[j][2] - mn1);
                sacc[j][3] = exp2f(sacc[j][3] - mn1);
                rs0 += sacc[j][0] + sacc[j][1];
                rs1 += sacc[j][2] + sacc[j][3];
            }
            rs0 += __shfl_xor_sync(0xffffffffu, rs0, 1);
            rs0 += __shfl_xor_sync(0xffffffffu, rs0, 2);
            rs1 += __shfl_xor_sync(0xffffffffu, rs1, 1);
            rs1 += __shfl_xor_sync(0xffffffffu, rs1, 2);
            l0r = l0r * al0 + rs0;
            l1r = l1r * al1 + rs1;

            uint32_t pa[4][4];
            #pragma unroll
            for (int ks = 0; ks < 4; ks++) {
                __half2 h0 = __floats2half2_rn(sacc[2*ks][0],   sacc[2*ks][1]);
                __half2 h1 = __floats2half2_rn(sacc[2*ks][2],   sacc[2*ks][3]);
                __half2 h2 = __floats2half2_rn(sacc[2*ks+1][0], sacc[2*ks+1][1]);
                __half2 h3 = __floats2half2_rn(sacc[2*ks+1][2], sacc[2*ks+1][3]);
                pa[ks][0] = *(uint32_t*)&h0; pa[ks][1] = *(uint32_t*)&h1;
                pa[ks][2] = *(uint32_t*)&h2; pa[ks][3] = *(uint32_t*)&h3;
            }

            #pragma unroll
            for (int j = 0; j < 8; j++) {
                oacc[j][0] *= al0; oacc[j][1] *= al0;
                oacc[j][2] *= al1; oacc[j][3] *= al1;
            }
            #pragma unroll
            for (int ks = 0; ks < 4; ks++) {
                #pragma unroll
                for (int ng = 0; ng < 4; ng++) {
                    uint32_t b0, b1, b2, b3;
                    uint32_t addr = sv + ((ks * 16 + vk_row) * KS_STR + ng * 16 + vn_col) * 2;
                    ldsm_x4t(b0, b1, b2, b3, addr);
                    uint32_t bf0[2] = {b0, b1}, bf1[2] = {b2, b3};
                    mma16816h(oacc[ng * 2],     pa[ks], bf0);
                    mma16816h(oacc[ng * 2 + 1], pa[ks], bf1);
                }
            }
        }
    }

    const float il0 = 1.f / l0r;
    const float il1 = 1.f / l1r;
    __half* Og = O + ((size_t)(b * SEQ + q0 + wq)) * HDIM + h * HD;
    #pragma unroll
    for (int j = 0; j < 8; j++) {
        const int col = j * 8 + t * 2;
        *(__half2*)(Og + (size_t)g * HDIM + col) =
            __floats2half2_rn(oacc[j][0] * il0, oacc[j][1] * il0);
        *(__half2*)(Og + (size_t)(g + 8) * HDIM + col) =
            __floats2half2_rn(oacc[j][2] * il1, oacc[j][3] * il1);
    }
}

// ---------------- Residual + LayerNorm ---------------------------------------
__global__ void __launch_bounds__(256) ln_kernel(
    const float* __restrict__ X, const float* __restrict__ Y,
    const float* __restrict__ g, const float* __restrict__ be,
    float* __restrict__ out)
{
    const int row = blockIdx.x;
    const int tid = threadIdx.x;
    const float* xr = X + (size_t)row * HDIM;
    const float* yr = Y + (size_t)row * HDIM;

    float4 x4 = *(const float4*)(xr + tid * 4);
    float4 y4 = *(const float4*)(yr + tid * 4);
    float v0 = x4.x + y4.x, v1 = x4.y + y4.y, v2 = x4.z + y4.z, v3 = x4.w + y4.w;

    float s  = v0 + v1 + v2 + v3;
    float ss = v0 * v0 + v1 * v1 + v2 * v2 + v3 * v3;
    #pragma unroll
    for (int off = 16; off > 0; off >>= 1) {
        s  += __shfl_xor_sync(0xffffffffu, s, off);
        ss += __shfl_xor_sync(0xffffffffu, ss, off);
    }

    __shared__ float sbuf[8], ssbuf[8];
    __shared__ float mu_s, rstd_s;
    if ((tid & 31) == 0) { sbuf[tid >> 5] = s; ssbuf[tid >> 5] = ss; }
    __syncthreads();
    if (tid == 0) {
        float S = 0.f, SS = 0.f;
        #pragma unroll
        for (int k = 0; k < 8; k++) { S += sbuf[k]; SS += ssbuf[k]; }
        float mu = S * (1.0f / HDIM);
        float var = SS * (1.0f / HDIM) - mu * mu;
        mu_s = mu;
        rstd_s = rsqrtf(var + 1e-5f);
    }
    __syncthreads();
    float mu = mu_s, rs = rstd_s;

    float4 g4 = *(const float4*)(g + tid * 4);
    float4 b4 = *(const float4*)(be + tid * 4);
    float4 o;
    o.x = (v0 - mu) * rs * g4.x + b4.x;
    o.y = (v1 - mu) * rs * g4.y + b4.y;
    o.z = (v2 - mu) * rs * g4.z + b4.z;
    o.w = (v3 - mu) * rs * g4.w + b4.w;
    *(float4*)(out + (size_t)row * HDIM + tid * 4) = o;
}

// ---------------- launch -----------------------------------------------------
extern "C" void kernel_launch(void* const* d_in, const int* in_sizes, int n_in,
                              void* d_out, int out_size)
{
    const float* query = (const float*)d_in[0];
    const float* key   = (const float*)d_in[1];
    const float* value = (const float*)d_in[2];
    const float* Wq = (const float*)d_in[4];
    const float* bq = (const float*)d_in[5];
    const float* Wk = (const float*)d_in[6];
    const float* bk = (const float*)d_in[7];
    const float* Wv = (const float*)d_in[8];
    const float* bv = (const float*)d_in[9];
    const float* Wo = (const float*)d_in[10];
    const float* bo = (const float*)d_in[11];
    const float* lg = (const float*)d_in[12];
    const float* lb = (const float*)d_in[13];
    float* out = (float*)d_out;

    __half *dQh, *dKh, *dVh, *dAOh, *dqx, *dkx, *dvx, *dWq, *dWk, *dWv, *dWo;
    float *dY;
    cudaGetSymbolAddress((void**)&dQh, g_Qh);
    cudaGetSymbolAddress((void**)&dKh, g_Kh);
    cudaGetSymbolAddress((void**)&dVh, g_Vh);
    cudaGetSymbolAddress((void**)&dAOh, g_AOh);
    cudaGetSymbolAddress((void**)&dY,  g_Y);
    cudaGetSymbolAddress((void**)&dqx, g_qx);
    cudaGetSymbolAddress((void**)&dkx, g_kx);
    cudaGetSymbolAddress((void**)&dvx, g_vx);
    cudaGetSymbolAddress((void**)&dWq, g_Wqh);
    cudaGetSymbolAddress((void**)&dWk, g_Wkh);
    cudaGetSymbolAddress((void**)&dWv, g_Wvh);
    cudaGetSymbolAddress((void**)&dWo, g_Woh);

    const int nbig = MROWS * HDIM;
    const int nsmall = HDIM * HDIM;
    dim3 gCvt(nbig / (256 * 4), 7);
    cvt7<<<gCvt, 256>>>(query, key, value, Wq, Wk, Wv, Wo,
                        dqx, dkx, dvx, dWq, dWk, dWv, dWo, nbig, nsmall);

    const int gemm_smem = G_SMEM_HALVES * 2;      // bytes
    cudaFuncSetAttribute(gemm_qkv, cudaFuncAttributeMaxDynamicSharedMemorySize, gemm_smem);
    cudaFuncSetAttribute(gemm_o,   cudaFuncAttributeMaxDynamicSharedMemorySize, gemm_smem);
    const int attn_smem = A_SMEM_HALVES * 2;      // bytes
    cudaFuncSetAttribute(attn_fa, cudaFuncAttributeMaxDynamicSharedMemorySize, attn_smem);

    dim3 gQKV(HDIM / 128, MROWS / 128, 3);
    gemm_qkv<<<gQKV, 256, gemm_smem>>>(dqx, dkx, dvx, dWq, dWk, dWv,
                                       bq, bk, bv, dQh, dKh, dVh);

    attn_fa<<<dim3(SEQ / 128, NHEAD, BATCH), 256, attn_smem>>>(dQh, dKh, dVh, dAOh);

    dim3 gO(HDIM / 128, MROWS / 128);
    gemm_o<<<gO, 256, gemm_smem>>>(dAOh, dWo, bo, dY);

    ln_kernel<<<MROWS, 256>>>(query, dY, lg, lb, out);
}

// round 8
// speedup vs baseline: 1.4861x; 1.0102x over previous
#include <cuda_runtime.h>
#include <cuda_fp16.h>
#include <cstdint>

#define BATCH 2
#define SEQ   2048
#define HDIM  1024
#define NHEAD 16
#define HD    64
#define MROWS (BATCH * SEQ)   // 4096

// ---------------- scratch (device globals: allocation-free) ------------------
__device__ __half g_Qh[MROWS * HDIM];
__device__ __half g_Kh[MROWS * HDIM];
__device__ __half g_Vh[MROWS * HDIM];
__device__ __half g_AOh[MROWS * HDIM];
__device__ float  g_Y[MROWS * HDIM];
__device__ __half g_qx[MROWS * HDIM];
__device__ __half g_kx[MROWS * HDIM];
__device__ __half g_vx[MROWS * HDIM];
__device__ __half g_Wqh[HDIM * HDIM];
__device__ __half g_Wkh[HDIM * HDIM];
__device__ __half g_Wvh[HDIM * HDIM];
__device__ __half g_Woh[HDIM * HDIM];

// ---------------- helpers ----------------------------------------------------
__device__ __forceinline__ void mma16816h(float* c, const uint32_t* a, const uint32_t* b) {
    asm volatile(
        "mma.sync.aligned.m16n8k16.row.col.f32.f16.f16.f32 "
        "{%0,%1,%2,%3},{%4,%5,%6,%7},{%8,%9},{%0,%1,%2,%3};"
        : "+f"(c[0]), "+f"(c[1]), "+f"(c[2]), "+f"(c[3])
        : "r"(a[0]), "r"(a[1]), "r"(a[2]), "r"(a[3]), "r"(b[0]), "r"(b[1]));
}

__device__ __forceinline__ void ldsm_x4(uint32_t& r0, uint32_t& r1, uint32_t& r2,
                                        uint32_t& r3, uint32_t addr) {
    asm volatile("ldmatrix.sync.aligned.m8n8.x4.shared.b16 {%0,%1,%2,%3}, [%4];"
                 : "=r"(r0), "=r"(r1), "=r"(r2), "=r"(r3) : "r"(addr));
}
__device__ __forceinline__ void ldsm_x4t(uint32_t& r0, uint32_t& r1, uint32_t& r2,
                                         uint32_t& r3, uint32_t addr) {
    asm volatile("ldmatrix.sync.aligned.m8n8.x4.trans.shared.b16 {%0,%1,%2,%3}, [%4];"
                 : "=r"(r0), "=r"(r1), "=r"(r2), "=r"(r3) : "r"(addr));
}

__device__ __forceinline__ void cp16(uint32_t dst, const void* src) {
    asm volatile("cp.async.cg.shared.global [%0], [%1], 16;" :: "r"(dst), "l"(src));
}
__device__ __forceinline__ void cp_commit() {
    asm volatile("cp.async.commit_group;");
}
template <int N>
__device__ __forceinline__ void cp_wait() {
    asm volatile("cp.async.wait_group %0;" :: "n"(N));
}

// ---------------- fp32 -> fp16 batched convert --------------------------------
__global__ void __launch_bounds__(256) cvt7(
    const float* s0, const float* s1, const float* s2, const float* s3,
    const float* s4, const float* s5, const float* s6,
    __half* d0, __half* d1, __half* d2, __half* d3,
    __half* d4, __half* d5, __half* d6,
    int nbig, int nsmall)
{
    const float* s;
    __half* d;
    int n;
    switch (blockIdx.y) {
        case 0: s = s0; d = d0; n = nbig; break;
        case 1: s = s1; d = d1; n = nbig; break;
        case 2: s = s2; d = d2; n = nbig; break;
        case 3: s = s3; d = d3; n = nsmall; break;
        case 4: s = s4; d = d4; n = nsmall; break;
        case 5: s = s5; d = d5; n = nsmall; break;
        default: s = s6; d = d6; n = nsmall; break;
    }
    int idx = (blockIdx.x * 256 + threadIdx.x) * 4;
    if (idx < n) {
        float4 v = *(const float4*)(s + idx);
        *(__half2*)(d + idx)     = __floats2half2_rn(v.x, v.y);
        *(__half2*)(d + idx + 2) = __floats2half2_rn(v.z, v.w);
    }
}

// ---------------- fp16 GEMM: C[M,N] = A[M,K] @ W[N,K]^T + bias ---------------
// 256x128 CTA tile, BK=32, 3-stage cp.async ring, 8 warps (4x2), warp tile 64x64.
#define GHS 40                          // halves per 32-half smem row (80 B)
#define A_ST (256 * GHS)                // halves per A stage
#define B_ST (128 * GHS)                // halves per B stage
#define PAIR_ST (A_ST + B_ST)
#define G_SMEM_BYTES (3 * PAIR_ST * 2)  // 92160

template <typename OutT>
__device__ __forceinline__ void gemm_core(
    const __half* __restrict__ A, const __half* __restrict__ W,
    const float* __restrict__ bias, OutT* __restrict__ C,
    int M, int N, int K, __half* smem, int m0, int n0)
{
    const int tid  = threadIdx.x;
    const int w    = tid >> 5;
    const int lane = tid & 31;
    const int g    = lane >> 2;
    const int t    = lane & 3;
    const int wm   = (w >> 1) * 64;       // 0,64,128,192
    const int wn   = (w & 1) * 64;        // 0,64

    const uint32_t s_base = (uint32_t)__cvta_generic_to_shared(smem);

    const int a_row  = lane & 15;
    const int a_chi  = (lane >> 4) * 8;
    const int kn_row = (lane & 7) + ((lane >> 4) & 1) * 8;
    const int kn_col = ((lane >> 3) & 1) * 8;

    float acc[4][8][4];
    #pragma unroll
    for (int i = 0; i < 4; i++)
        #pragma unroll
        for (int j = 0; j < 8; j++)
            #pragma unroll
            for (int r = 0; r < 4; r++) acc[i][j][r] = 0.f;

    const int niter = K / 32;

    // per-stage load: A 1024 chunks (256 rows x 4), B 512 chunks; 6 per thread
    auto load_stage = [&](int stage, int kb) {
        const uint32_t sa = s_base + (uint32_t)stage * (PAIR_ST * 2);
        const uint32_t sb = sa + A_ST * 2;
        #pragma unroll
        for (int j = 0; j < 6; j++) {
            int cid = tid + j * 256;            // 0..1535
            if (cid < 1024) {
                int r  = cid >> 2;
                int ch = (cid & 3) * 8;
                cp16(sa + (r * GHS + ch) * 2,
                     A + (size_t)(m0 + r) * K + kb * 32 + ch);
            } else {
                int c2 = cid - 1024;
                int r  = c2 >> 2;
                int ch = (c2 & 3) * 8;
                cp16(sb + (r * GHS + ch) * 2,
                     W + (size_t)(n0 + r) * K + kb * 32 + ch);
            }
        }
    };

    load_stage(0, 0); cp_commit();
    load_stage(1, 1); cp_commit();

    for (int kb = 0; kb < niter; kb++) {
        cp_wait<1>();
        __syncthreads();

        if (kb + 2 < niter) load_stage((kb + 2) % 3, kb + 2);
        cp_commit();

        const int cs = kb % 3;
        const uint32_t sa = s_base + (uint32_t)cs * (PAIR_ST * 2);
        const uint32_t sb = sa + A_ST * 2;

        #pragma unroll
        for (int ks = 0; ks < 2; ks++) {
            const int k0 = ks * 16;
            uint32_t af[4][4];
            #pragma unroll
            for (int mt = 0; mt < 4; mt++) {
                uint32_t addr = sa + ((wm + mt * 16 + a_row) * GHS + k0 + a_chi) * 2;
                ldsm_x4(af[mt][0], af[mt][1], af[mt][2], af[mt][3], addr);
            }
            uint32_t bfr[4][4];
            #pragma unroll
            for (int ng = 0; ng < 4; ng++) {
                uint32_t addr = sb + ((wn + ng * 16 + kn_row) * GHS + k0 + kn_col) * 2;
                ldsm_x4(bfr[ng][0], bfr[ng][1], bfr[ng][2], bfr[ng][3], addr);
            }
            #pragma unroll
            for (int mt = 0; mt < 4; mt++)
                #pragma unroll
                for (int nt = 0; nt < 8; nt++) {
                    uint32_t bf[2] = {bfr[nt >> 1][(nt & 1) * 2],
                                      bfr[nt >> 1][(nt & 1) * 2 + 1]};
                    mma16816h(acc[mt][nt], af[mt], bf);
                }
        }
    }

    #pragma unroll
    for (int mt = 0; mt < 4; mt++) {
        const int row0 = m0 + wm + mt * 16 + g;
        const int row1 = row0 + 8;
        #pragma unroll
        for (int nt = 0; nt < 8; nt++) {
            const int col = n0 + wn + nt * 8 + t * 2;
            const float b0 = bias[col], b1 = bias[col + 1];
            float c00 = acc[mt][nt][0] + b0, c01 = acc[mt][nt][1] + b1;
            float c10 = acc[mt][nt][2] + b0, c11 = acc[mt][nt][3] + b1;
            if constexpr (sizeof(OutT) == 4) {
                *(float2*)((float*)C + (size_t)row0 * N + col) = make_float2(c00, c01);
                *(float2*)((float*)C + (size_t)row1 * N + col) = make_float2(c10, c11);
            } else {
                *(__half2*)((__half*)C + (size_t)row0 * N + col) = __floats2half2_rn(c00, c01);
                *(__half2*)((__half*)C + (size_t)row1 * N + col) = __floats2half2_rn(c10, c11);
            }
        }
    }
}

__global__ void __launch_bounds__(256, 1) gemm_qkv(
    const __half* Aq, const __half* Ak, const __half* Av,
    const __half* Wq, const __half* Wk, const __half* Wv,
    const float* bq, const float* bk, const float* bv,
    __half* Cq, __half* Ck, __half* Cv)
{
    extern __shared__ __half gsm[];
    const int z = blockIdx.z;
    const __half* A = (z == 0) ? Aq : (z == 1) ? Ak : Av;
    const __half* W = (z == 0) ? Wq : (z == 1) ? Wk : Wv;
    const float*  b = (z == 0) ? bq : (z == 1) ? bk : bv;
    __half*       C = (z == 0) ? Cq : (z == 1) ? Ck : Cv;
    gemm_core<__half>(A, W, b, C, MROWS, HDIM, HDIM, gsm,
                      blockIdx.y * 256, blockIdx.x * 128);
}

__global__ void __launch_bounds__(256, 1) gemm_o(
    const __half* A, const __half* W, const float* bias, float* C)
{
    extern __shared__ __half gsm[];
    gemm_core<float>(A, W, bias, C, MROWS, HDIM, HDIM, gsm,
                     blockIdx.y * 256, blockIdx.x * 128);
}

// ---------------- FA2-style fp16 flash attention (causal) --------------------
#define KS_STR 72
#define A_STAGE (64 * KS_STR)
#define A_SMEM_HALVES (3 * 2 * A_STAGE)

__global__ void __launch_bounds__(256) attn_fa(
    const __half* __restrict__ Qh, const __half* __restrict__ Kh,
    const __half* __restrict__ Vh, __half* __restrict__ O)
{
    extern __shared__ __half asm_[];
    __half* Ks = asm_;
    __half* Vs = asm_ + 3 * A_STAGE;

    const int tid  = threadIdx.x;
    const int w    = tid >> 5;
    const int lane = tid & 31;
    const int g    = lane >> 2;
    const int t    = lane & 3;
    const int wq   = w * 16;

    const int q0 = (gridDim.x - 1 - blockIdx.x) * 128;
    const int h  = blockIdx.y;
    const int b  = blockIdx.z;

    const uint32_t ks_base = (uint32_t)__cvta_generic_to_shared(Ks);
    const uint32_t vs_base = (uint32_t)__cvta_generic_to_shared(Vs);
    const uint32_t stage_b = A_STAGE * 2;

    const __half* Qg = Qh + ((size_t)(b * SEQ + q0)) * HDIM + h * HD;
    #pragma unroll
    for (int j = 0; j < 4; j++) {
        int i = tid + j * 256;
        int r = i >> 3;
        int c8 = (i & 7) * 8;
        cp16(ks_base + (r * KS_STR + c8) * 2, Qg + (size_t)r * HDIM + c8);
    }
    cp_commit();
    cp_wait<0>();
    __syncthreads();

    uint32_t qf[4][4];
    {
        const __half2 sc = __half2half2(__float2half(0.125f * 1.44269504f));
        const int row = wq + (lane & 15);
        const int chi = (lane >> 4) * 8;
        #pragma unroll
        for (int ks = 0; ks < 4; ks++) {
            uint32_t addr = ks_base + (row * KS_STR + ks * 16 + chi) * 2;
            ldsm_x4(qf[ks][0], qf[ks][1], qf[ks][2], qf[ks][3], addr);
            #pragma unroll
            for (int r = 0; r < 4; r++) {
                __half2 v = *(__half2*)&qf[ks][r];
                v = __hmul2(v, sc);
                qf[ks][r] = *(uint32_t*)&v;
            }
        }
    }
    __syncthreads();

    float m0r = -1e30f, m1r = -1e30f, l0r = 0.f, l1r = 0.f;
    float oacc[8][4];
    #pragma unroll
    for (int j = 0; j < 8; j++)
        #pragma unroll
        for (int r = 0; r < 4; r++) oacc[j][r] = 0.f;

    const int kn_row = (lane & 7) + ((lane >> 4) & 1) * 8;
    const int kn_col = ((lane >> 3) & 1) * 8;
    const int vk_row = (lane & 7) + ((lane >> 3) & 1) * 8;
    const int vn_col = (lane >> 4) * 8;

    const int jmax = (q0 + 127) / 64;

    #pragma unroll
    for (int p = 0; p < 2; p++) {
        if (p <= jmax) {
            const uint32_t st = p * stage_b;
            const __half* Kg = Kh + ((size_t)(b * SEQ + p * 64)) * HDIM + h * HD;
            const __half* Vg = Vh + ((size_t)(b * SEQ + p * 64)) * HDIM + h * HD;
            #pragma unroll
            for (int j = 0; j < 2; j++) {
                int i = tid + j * 256;
                int r = i >> 3;
                int c8 = (i & 7) * 8;
                cp16(ks_base + st + (r * KS_STR + c8) * 2, Kg + (size_t)r * HDIM + c8);
                cp16(vs_base + st + (r * KS_STR + c8) * 2, Vg + (size_t)r * HDIM + c8);
            }
        }
        cp_commit();
    }

    for (int jt = 0; jt <= jmax; jt++) {
        const int k0g = jt * 64;

        cp_wait<1>();
        __syncthreads();

        if (jt + 2 <= jmax) {
            const int s = (jt + 2) % 3;
            const uint32_t st = s * stage_b;
            const __half* Kg = Kh + ((size_t)(b * SEQ + (jt + 2) * 64)) * HDIM + h * HD;
            const __half* Vg = Vh + ((size_t)(b * SEQ + (jt + 2) * 64)) * HDIM + h * HD;
            #pragma unroll
            for (int j = 0; j < 2; j++) {
                int i = tid + j * 256;
                int r = i >> 3;
                int c8 = (i & 7) * 8;
                cp16(ks_base + st + (r * KS_STR + c8) * 2, Kg + (size_t)r * HDIM + c8);
                cp16(vs_base + st + (r * KS_STR + c8) * 2, Vg + (size_t)r * HDIM + c8);
            }
        }
        cp_commit();

        const uint32_t sk = ks_base + (jt % 3) * stage_b;
        const uint32_t sv = vs_base + (jt % 3) * stage_b;

        const bool active = (k0g <= q0 + wq + 15);
        if (active) {
            float sacc[8][4];
            #pragma unroll
            for (int j = 0; j < 8; j++)
                #pragma unroll
                for (int r = 0; r < 4; r++) sacc[j][r] = 0.f;

            #pragma unroll
            for (int ks = 0; ks < 4; ks++) {
                #pragma unroll
                for (int ng = 0; ng < 4; ng++) {
                    uint32_t b0, b1, b2, b3;
                    uint32_t addr = sk + ((ng * 16 + kn_row) * KS_STR + ks * 16 + kn_col) * 2;
                    ldsm_x4(b0, b1, b2, b3, addr);
                    uint32_t bf0[2] = {b0, b1}, bf1[2] = {b2, b3};
                    mma16816h(sacc[ng * 2],     qf[ks], bf0);
                    mma16816h(sacc[ng * 2 + 1], qf[ks], bf1);
                }
            }

            if (k0g + 63 > q0 + wq) {
                const int row0 = q0 + wq + g;
                const int row1 = row0 + 8;
                #pragma unroll
                for (int j = 0; j < 8; j++) {
                    const int col = k0g + j * 8 + t * 2;
                    if (col > row0)     sacc[j][0] = -1e30f;
                    if (col + 1 > row0) sacc[j][1] = -1e30f;
                    if (col > row1)     sacc[j][2] = -1e30f;
                    if (col + 1 > row1) sacc[j][3] = -1e30f;
                }
            }

            float tm0 = -1e30f, tm1 = -1e30f;
            #pragma unroll
            for (int j = 0; j < 8; j++) {
                tm0 = fmaxf(tm0, fmaxf(sacc[j][0], sacc[j][1]));
                tm1 = fmaxf(tm1, fmaxf(sacc[j][2], sacc[j][3]));
            }
            tm0 = fmaxf(tm0, __shfl_xor_sync(0xffffffffu, tm0, 1));
            tm0 = fmaxf(tm0, __shfl_xor_sync(0xffffffffu, tm0, 2));
            tm1 = fmaxf(tm1, __shfl_xor_sync(0xffffffffu, tm1, 1));
            tm1 = fmaxf(tm1, __shfl_xor_sync(0xffffffffu, tm1, 2));

            const float mn0 = fmaxf(m0r, tm0);
            const float mn1 = fmaxf(m1r, tm1);
            const float al0 = exp2f(m0r - mn0);
            const float al1 = exp2f(m1r - mn1);
            m0r = mn0; m1r = mn1;

            float rs0 = 0.f, rs1 = 0.f;
            #pragma unroll
            for (int j = 0; j < 8; j++) {
                sacc[j][0] = exp2f(sacc[j][0] - mn0);
                sacc[j][1] = exp2f(sacc[j][1] - mn0);
                sacc[j][2] = exp2f(sacc[j][2] - mn1);
                sacc[j][3] = exp2f(sacc[j][3] - mn1);
                rs0 += sacc[j][0] + sacc[j][1];
                rs1 += sacc[j][2] + sacc[j][3];
            }
            rs0 += __shfl_xor_sync(0xffffffffu, rs0, 1);
            rs0 += __shfl_xor_sync(0xffffffffu, rs0, 2);
            rs1 += __shfl_xor_sync(0xffffffffu, rs1, 1);
            rs1 += __shfl_xor_sync(0xffffffffu, rs1, 2);
            l0r = l0r * al0 + rs0;
            l1r = l1r * al1 + rs1;

            uint32_t pa[4][4];
            #pragma unroll
            for (int ks = 0; ks < 4; ks++) {
                __half2 h0 = __floats2half2_rn(sacc[2*ks][0],   sacc[2*ks][1]);
                __half2 h1 = __floats2half2_rn(sacc[2*ks][2],   sacc[2*ks][3]);
                __half2 h2 = __floats2half2_rn(sacc[2*ks+1][0], sacc[2*ks+1][1]);
                __half2 h3 = __floats2half2_rn(sacc[2*ks+1][2], sacc[2*ks+1][3]);
                pa[ks][0] = *(uint32_t*)&h0; pa[ks][1] = *(uint32_t*)&h1;
                pa[ks][2] = *(uint32_t*)&h2; pa[ks][3] = *(uint32_t*)&h3;
            }

            #pragma unroll
            for (int j = 0; j < 8; j++) {
                oacc[j][0] *= al0; oacc[j][1] *= al0;
                oacc[j][2] *= al1; oacc[j][3] *= al1;
            }
            #pragma unroll
            for (int ks = 0; ks < 4; ks++) {
                #pragma unroll
                for (int ng = 0; ng < 4; ng++) {
                    uint32_t b0, b1, b2, b3;
                    uint32_t addr = sv + ((ks * 16 + vk_row) * KS_STR + ng * 16 + vn_col) * 2;
                    ldsm_x4t(b0, b1, b2, b3, addr);
                    uint32_t bf0[2] = {b0, b1}, bf1[2] = {b2, b3};
                    mma16816h(oacc[ng * 2],     pa[ks], bf0);
                    mma16816h(oacc[ng * 2 + 1], pa[ks], bf1);
                }
            }
        }
    }

    const float il0 = 1.f / l0r;
    const float il1 = 1.f / l1r;
    __half* Og = O + ((size_t)(b * SEQ + q0 + wq)) * HDIM + h * HD;
    #pragma unroll
    for (int j = 0; j < 8; j++) {
        const int col = j * 8 + t * 2;
        *(__half2*)(Og + (size_t)g * HDIM + col) =
            __floats2half2_rn(oacc[j][0] * il0, oacc[j][1] * il0);
        *(__half2*)(Og + (size_t)(g + 8) * HDIM + col) =
            __floats2half2_rn(oacc[j][2] * il1, oacc[j][3] * il1);
    }
}

// ---------------- Residual + LayerNorm ---------------------------------------
__global__ void __launch_bounds__(256) ln_kernel(
    const float* __restrict__ X, const float* __restrict__ Y,
    const float* __restrict__ g, const float* __restrict__ be,
    float* __restrict__ out)
{
    const int row = blockIdx.x;
    const int tid = threadIdx.x;
    const float* xr = X + (size_t)row * HDIM;
    const float* yr = Y + (size_t)row * HDIM;

    float4 x4 = *(const float4*)(xr + tid * 4);
    float4 y4 = *(const float4*)(yr + tid * 4);
    float v0 = x4.x + y4.x, v1 = x4.y + y4.y, v2 = x4.z + y4.z, v3 = x4.w + y4.w;

    float s  = v0 + v1 + v2 + v3;
    float ss = v0 * v0 + v1 * v1 + v2 * v2 + v3 * v3;
    #pragma unroll
    for (int off = 16; off > 0; off >>= 1) {
        s  += __shfl_xor_sync(0xffffffffu, s, off);
        ss += __shfl_xor_sync(0xffffffffu, ss, off);
    }

    __shared__ float sbuf[8], ssbuf[8];
    __shared__ float mu_s, rstd_s;
    if ((tid & 31) == 0) { sbuf[tid >> 5] = s; ssbuf[tid >> 5] = ss; }
    __syncthreads();
    if (tid == 0) {
        float S = 0.f, SS = 0.f;
        #pragma unroll
        for (int k = 0; k < 8; k++) { S += sbuf[k]; SS += ssbuf[k]; }
        float mu = S * (1.0f / HDIM);
        float var = SS * (1.0f / HDIM) - mu * mu;
        mu_s = mu;
        rstd_s = rsqrtf(var + 1e-5f);
    }
    __syncthreads();
    float mu = mu_s, rs = rstd_s;

    float4 g4 = *(const float4*)(g + tid * 4);
    float4 b4 = *(const float4*)(be + tid * 4);
    float4 o;
    o.x = (v0 - mu) * rs * g4.x + b4.x;
    o.y = (v1 - mu) * rs * g4.y + b4.y;
    o.z = (v2 - mu) * rs * g4.z + b4.z;
    o.w = (v3 - mu) * rs * g4.w + b4.w;
    *(float4*)(out + (size_t)row * HDIM + tid * 4) = o;
}

// ---------------- launch -----------------------------------------------------
extern "C" void kernel_launch(void* const* d_in, const int* in_sizes, int n_in,
                              void* d_out, int out_size)
{
    const float* query = (const float*)d_in[0];
    const float* key   = (const float*)d_in[1];
    const float* value = (const float*)d_in[2];
    const float* Wq = (const float*)d_in[4];
    const float* bq = (const float*)d_in[5];
    const float* Wk = (const float*)d_in[6];
    const float* bk = (const float*)d_in[7];
    const float* Wv = (const float*)d_in[8];
    const float* bv = (const float*)d_in[9];
    const float* Wo = (const float*)d_in[10];
    const float* bo = (const float*)d_in[11];
    const float* lg = (const float*)d_in[12];
    const float* lb = (const float*)d_in[13];
    float* out = (float*)d_out;

    __half *dQh, *dKh, *dVh, *dAOh, *dqx, *dkx, *dvx, *dWq, *dWk, *dWv, *dWo;
    float *dY;
    cudaGetSymbolAddress((void**)&dQh, g_Qh);
    cudaGetSymbolAddress((void**)&dKh, g_Kh);
    cudaGetSymbolAddress((void**)&dVh, g_Vh);
    cudaGetSymbolAddress((void**)&dAOh, g_AOh);
    cudaGetSymbolAddress((void**)&dY,  g_Y);
    cudaGetSymbolAddress((void**)&dqx, g_qx);
    cudaGetSymbolAddress((void**)&dkx, g_kx);
    cudaGetSymbolAddress((void**)&dvx, g_vx);
    cudaGetSymbolAddress((void**)&dWq, g_Wqh);
    cudaGetSymbolAddress((void**)&dWk, g_Wkh);
    cudaGetSymbolAddress((void**)&dWv, g_Wvh);
    cudaGetSymbolAddress((void**)&dWo, g_Woh);

    const int nbig = MROWS * HDIM;
    const int nsmall = HDIM * HDIM;
    dim3 gCvt(nbig / (256 * 4), 7);
    cvt7<<<gCvt, 256>>>(query, key, value, Wq, Wk, Wv, Wo,
                        dqx, dkx, dvx, dWq, dWk, dWv, dWo, nbig, nsmall);

    cudaFuncSetAttribute(gemm_qkv, cudaFuncAttributeMaxDynamicSharedMemorySize, G_SMEM_BYTES);
    cudaFuncSetAttribute(gemm_o,   cudaFuncAttributeMaxDynamicSharedMemorySize, G_SMEM_BYTES);
    const int attn_smem = A_SMEM_HALVES * 2;
    cudaFuncSetAttribute(attn_fa, cudaFuncAttributeMaxDynamicSharedMemorySize, attn_smem);

    dim3 gQKV(HDIM / 128, MROWS / 256, 3);           // (8, 16, 3)
    gemm_qkv<<<gQKV, 256, G_SMEM_BYTES>>>(dqx, dkx, dvx, dWq, dWk, dWv,
                                          bq, bk, bv, dQh, dKh, dVh);

    attn_fa<<<dim3(SEQ / 128, NHEAD, BATCH), 256, attn_smem>>>(dQh, dKh, dVh, dAOh);

    dim3 gO(HDIM / 128, MROWS / 256);                // (8, 16)
    gemm_o<<<gO, 256, G_SMEM_BYTES>>>(dAOh, dWo, bo, dY);

    ln_kernel<<<MROWS, 256>>>(query, dY, lg, lb, out);
}

// round 9
// speedup vs baseline: 1.5173x; 1.0210x over previous
#include <cuda_runtime.h>
#include <cuda_fp16.h>
#include <cstdint>

#define BATCH 2
#define SEQ   2048
#define HDIM  1024
#define NHEAD 16
#define HD    64
#define MROWS (BATCH * SEQ)   // 4096

// ---------------- scratch (device globals: allocation-free) ------------------
__device__ __half g_Qh[MROWS * HDIM];
__device__ __half g_Kh[MROWS * HDIM];
__device__ __half g_Vh[MROWS * HDIM];
__device__ __half g_AOh[MROWS * HDIM];
__device__ float  g_Y[MROWS * HDIM];
__device__ __half g_qx[MROWS * HDIM];
__device__ __half g_kx[MROWS * HDIM];
__device__ __half g_vx[MROWS * HDIM];
__device__ __half g_Wqh[HDIM * HDIM];
__device__ __half g_Wkh[HDIM * HDIM];
__device__ __half g_Wvh[HDIM * HDIM];
__device__ __half g_Woh[HDIM * HDIM];

// ---------------- helpers ----------------------------------------------------
__device__ __forceinline__ void mma16816h(float* c, const uint32_t* a, const uint32_t* b) {
    asm volatile(
        "mma.sync.aligned.m16n8k16.row.col.f32.f16.f16.f32 "
        "{%0,%1,%2,%3},{%4,%5,%6,%7},{%8,%9},{%0,%1,%2,%3};"
        : "+f"(c[0]), "+f"(c[1]), "+f"(c[2]), "+f"(c[3])
        : "r"(a[0]), "r"(a[1]), "r"(a[2]), "r"(a[3]), "r"(b[0]), "r"(b[1]));
}

__device__ __forceinline__ void ldsm_x4(uint32_t& r0, uint32_t& r1, uint32_t& r2,
                                        uint32_t& r3, uint32_t addr) {
    asm volatile("ldmatrix.sync.aligned.m8n8.x4.shared.b16 {%0,%1,%2,%3}, [%4];"
                 : "=r"(r0), "=r"(r1), "=r"(r2), "=r"(r3) : "r"(addr));
}
__device__ __forceinline__ void ldsm_x4t(uint32_t& r0, uint32_t& r1, uint32_t& r2,
                                         uint32_t& r3, uint32_t addr) {
    asm volatile("ldmatrix.sync.aligned.m8n8.x4.trans.shared.b16 {%0,%1,%2,%3}, [%4];"
                 : "=r"(r0), "=r"(r1), "=r"(r2), "=r"(r3) : "r"(addr));
}

__device__ __forceinline__ void cp16(uint32_t dst, const void* src) {
    asm volatile("cp.async.cg.shared.global [%0], [%1], 16;" :: "r"(dst), "l"(src));
}
__device__ __forceinline__ void cp_commit() {
    asm volatile("cp.async.commit_group;");
}
template <int N>
__device__ __forceinline__ void cp_wait() {
    asm volatile("cp.async.wait_group %0;" :: "n"(N));
}

// ---------------- fp32 -> fp16 batched convert --------------------------------
__global__ void __launch_bounds__(256) cvt7(
    const float* s0, const float* s1, const float* s2, const float* s3,
    const float* s4, const float* s5, const float* s6,
    __half* d0, __half* d1, __half* d2, __half* d3,
    __half* d4, __half* d5, __half* d6,
    int nbig, int nsmall)
{
    const float* s;
    __half* d;
    int n;
    switch (blockIdx.y) {
        case 0: s = s0; d = d0; n = nbig; break;
        case 1: s = s1; d = d1; n = nbig; break;
        case 2: s = s2; d = d2; n = nbig; break;
        case 3: s = s3; d = d3; n = nsmall; break;
        case 4: s = s4; d = d4; n = nsmall; break;
        case 5: s = s5; d = d5; n = nsmall; break;
        default: s = s6; d = d6; n = nsmall; break;
    }
    int idx = (blockIdx.x * 256 + threadIdx.x) * 4;
    if (idx < n) {
        float4 v = *(const float4*)(s + idx);
        *(__half2*)(d + idx)     = __floats2half2_rn(v.x, v.y);
        *(__half2*)(d + idx + 2) = __floats2half2_rn(v.z, v.w);
    }
}

// ---------------- fp16 GEMM: C[M,N] = A[M,K] @ W[N,K]^T + bias ---------------
// 256x128 CTA tile, BK=32, 3-stage cp.async ring, 16 warps (4x4), warp 64x32.
#define GHS 40                          // halves per 32-half smem row (80 B)
#define A_ST (256 * GHS)                // halves per A stage
#define B_ST (128 * GHS)                // halves per B stage
#define PAIR_ST (A_ST + B_ST)
#define G_SMEM_BYTES (3 * PAIR_ST * 2)  // 92160

template <typename OutT>
__device__ __forceinline__ void gemm_core(
    const __half* __restrict__ A, const __half* __restrict__ W,
    const float* __restrict__ bias, OutT* __restrict__ C,
    int M, int N, int K, __half* smem, int m0, int n0)
{
    const int tid  = threadIdx.x;
    const int w    = tid >> 5;
    const int lane = tid & 31;
    const int g    = lane >> 2;
    const int t    = lane & 3;
    const int wm   = (w >> 2) * 64;       // 0,64,128,192
    const int wn   = (w & 3) * 32;        // 0,32,64,96

    const uint32_t s_base = (uint32_t)__cvta_generic_to_shared(smem);

    const int a_row  = lane & 15;
    const int a_chi  = (lane >> 4) * 8;
    const int kn_row = (lane & 7) + ((lane >> 4) & 1) * 8;
    const int kn_col = ((lane >> 3) & 1) * 8;

    float acc[4][4][4];
    #pragma unroll
    for (int i = 0; i < 4; i++)
        #pragma unroll
        for (int j = 0; j < 4; j++)
            #pragma unroll
            for (int r = 0; r < 4; r++) acc[i][j][r] = 0.f;

    const int niter = K / 32;

    // per-stage load: A 1024 chunks (256 rows x 4) + B 512 chunks; 3 per thread
    auto load_stage = [&](int stage, int kb) {
        const uint32_t sa = s_base + (uint32_t)stage * (PAIR_ST * 2);
        const uint32_t sb = sa + A_ST * 2;
        #pragma unroll
        for (int j = 0; j < 3; j++) {
            int cid = tid + j * 512;            // 0..1535
            if (cid < 1024) {
                int r  = cid >> 2;
                int ch = (cid & 3) * 8;
                cp16(sa + (r * GHS + ch) * 2,
                     A + (size_t)(m0 + r) * K + kb * 32 + ch);
            } else {
                int c2 = cid - 1024;
                int r  = c2 >> 2;
                int ch = (c2 & 3) * 8;
                cp16(sb + (r * GHS + ch) * 2,
                     W + (size_t)(n0 + r) * K + kb * 32 + ch);
            }
        }
    };

    load_stage(0, 0); cp_commit();
    load_stage(1, 1); cp_commit();

    for (int kb = 0; kb < niter; kb++) {
        cp_wait<1>();
        __syncthreads();

        if (kb + 2 < niter) load_stage((kb + 2) % 3, kb + 2);
        cp_commit();

        const int cs = kb % 3;
        const uint32_t sa = s_base + (uint32_t)cs * (PAIR_ST * 2);
        const uint32_t sb = sa + A_ST * 2;

        #pragma unroll
        for (int ks = 0; ks < 2; ks++) {
            const int k0 = ks * 16;
            // batch all fragment loads for this k-step first
            uint32_t af[4][4];
            #pragma unroll
            for (int mt = 0; mt < 4; mt++) {
                uint32_t addr = sa + ((wm + mt * 16 + a_row) * GHS + k0 + a_chi) * 2;
                ldsm_x4(af[mt][0], af[mt][1], af[mt][2], af[mt][3], addr);
            }
            uint32_t bfr[2][4];
            #pragma unroll
            for (int ng = 0; ng < 2; ng++) {
                uint32_t addr = sb + ((wn + ng * 16 + kn_row) * GHS + k0 + kn_col) * 2;
                ldsm_x4(bfr[ng][0], bfr[ng][1], bfr[ng][2], bfr[ng][3], addr);
            }
            // then 16 MMAs
            #pragma unroll
            for (int mt = 0; mt < 4; mt++)
                #pragma unroll
                for (int nt = 0; nt < 4; nt++) {
                    uint32_t bf[2] = {bfr[nt >> 1][(nt & 1) * 2],
                                      bfr[nt >> 1][(nt & 1) * 2 + 1]};
                    mma16816h(acc[mt][nt], af[mt], bf);
                }
        }
    }

    #pragma unroll
    for (int mt = 0; mt < 4; mt++) {
        const int row0 = m0 + wm + mt * 16 + g;
        const int row1 = row0 + 8;
        #pragma unroll
        for (int nt = 0; nt < 4; nt++) {
            const int col = n0 + wn + nt * 8 + t * 2;
            const float b0 = bias[col], b1 = bias[col + 1];
            float c00 = acc[mt][nt][0] + b0, c01 = acc[mt][nt][1] + b1;
            float c10 = acc[mt][nt][2] + b0, c11 = acc[mt][nt][3] + b1;
            if constexpr (sizeof(OutT) == 4) {
                *(float2*)((float*)C + (size_t)row0 * N + col) = make_float2(c00, c01);
                *(float2*)((float*)C + (size_t)row1 * N + col) = make_float2(c10, c11);
            } else {
                *(__half2*)((__half*)C + (size_t)row0 * N + col) = __floats2half2_rn(c00, c01);
                *(__half2*)((__half*)C + (size_t)row1 * N + col) = __floats2half2_rn(c10, c11);
            }
        }
    }
}

__global__ void __launch_bounds__(512, 1) gemm_qkv(
    const __half* Aq, const __half* Ak, const __half* Av,
    const __half* Wq, const __half* Wk, const __half* Wv,
    const float* bq, const float* bk, const float* bv,
    __half* Cq, __half* Ck, __half* Cv)
{
    extern __shared__ __half gsm[];
    const int z = blockIdx.z;
    const __half* A = (z == 0) ? Aq : (z == 1) ? Ak : Av;
    const __half* W = (z == 0) ? Wq : (z == 1) ? Wk : Wv;
    const float*  b = (z == 0) ? bq : (z == 1) ? bk : bv;
    __half*       C = (z == 0) ? Cq : (z == 1) ? Ck : Cv;
    gemm_core<__half>(A, W, b, C, MROWS, HDIM, HDIM, gsm,
                      blockIdx.y * 256, blockIdx.x * 128);
}

__global__ void __launch_bounds__(512, 1) gemm_o(
    const __half* A, const __half* W, const float* bias, float* C)
{
    extern __shared__ __half gsm[];
    gemm_core<float>(A, W, bias, C, MROWS, HDIM, HDIM, gsm,
                     blockIdx.y * 256, blockIdx.x * 128);
}

// ---------------- FA2-style fp16 flash attention (causal) --------------------
#define KS_STR 72
#define A_STAGE (64 * KS_STR)
#define A_SMEM_HALVES (3 * 2 * A_STAGE)

__global__ void __launch_bounds__(256) attn_fa(
    const __half* __restrict__ Qh, const __half* __restrict__ Kh,
    const __half* __restrict__ Vh, __half* __restrict__ O)
{
    extern __shared__ __half asm_[];
    __half* Ks = asm_;
    __half* Vs = asm_ + 3 * A_STAGE;

    const int tid  = threadIdx.x;
    const int w    = tid >> 5;
    const int lane = tid & 31;
    const int g    = lane >> 2;
    const int t    = lane & 3;
    const int wq   = w * 16;

    const int q0 = (gridDim.x - 1 - blockIdx.x) * 128;
    const int h  = blockIdx.y;
    const int b  = blockIdx.z;

    const uint32_t ks_base = (uint32_t)__cvta_generic_to_shared(Ks);
    const uint32_t vs_base = (uint32_t)__cvta_generic_to_shared(Vs);
    const uint32_t stage_b = A_STAGE * 2;

    const __half* Qg = Qh + ((size_t)(b * SEQ + q0)) * HDIM + h * HD;
    #pragma unroll
    for (int j = 0; j < 4; j++) {
        int i = tid + j * 256;
        int r = i >> 3;
        int c8 = (i & 7) * 8;
        cp16(ks_base + (r * KS_STR + c8) * 2, Qg + (size_t)r * HDIM + c8);
    }
    cp_commit();
    cp_wait<0>();
    __syncthreads();

    uint32_t qf[4][4];
    {
        const __half2 sc = __half2half2(__float2half(0.125f * 1.44269504f));
        const int row = wq + (lane & 15);
        const int chi = (lane >> 4) * 8;
        #pragma unroll
        for (int ks = 0; ks < 4; ks++) {
            uint32_t addr = ks_base + (row * KS_STR + ks * 16 + chi) * 2;
            ldsm_x4(qf[ks][0], qf[ks][1], qf[ks][2], qf[ks][3], addr);
            #pragma unroll
            for (int r = 0; r < 4; r++) {
                __half2 v = *(__half2*)&qf[ks][r];
                v = __hmul2(v, sc);
                qf[ks][r] = *(uint32_t*)&v;
            }
        }
    }
    __syncthreads();

    float m0r = -1e30f, m1r = -1e30f, l0r = 0.f, l1r = 0.f;
    float oacc[8][4];
    #pragma unroll
    for (int j = 0; j < 8; j++)
        #pragma unroll
        for (int r = 0; r < 4; r++) oacc[j][r] = 0.f;

    const int kn_row = (lane & 7) + ((lane >> 4) & 1) * 8;
    const int kn_col = ((lane >> 3) & 1) * 8;
    const int vk_row = (lane & 7) + ((lane >> 3) & 1) * 8;
    const int vn_col = (lane >> 4) * 8;

    const int jmax = (q0 + 127) / 64;

    #pragma unroll
    for (int p = 0; p < 2; p++) {
        if (p <= jmax) {
            const uint32_t st = p * stage_b;
            const __half* Kg = Kh + ((size_t)(b * SEQ + p * 64)) * HDIM + h * HD;
            const __half* Vg = Vh + ((size_t)(b * SEQ + p * 64)) * HDIM + h * HD;
            #pragma unroll
            for (int j = 0; j < 2; j++) {
                int i = tid + j * 256;
                int r = i >> 3;
                int c8 = (i & 7) * 8;
                cp16(ks_base + st + (r * KS_STR + c8) * 2, Kg + (size_t)r * HDIM + c8);
                cp16(vs_base + st + (r * KS_STR + c8) * 2, Vg + (size_t)r * HDIM + c8);
            }
        }
        cp_commit();
    }

    for (int jt = 0; jt <= jmax; jt++) {
        const int k0g = jt * 64;

        cp_wait<1>();
        __syncthreads();

        if (jt + 2 <= jmax) {
            const int s = (jt + 2) % 3;
            const uint32_t st = s * stage_b;
            const __half* Kg = Kh + ((size_t)(b * SEQ + (jt + 2) * 64)) * HDIM + h * HD;
            const __half* Vg = Vh + ((size_t)(b * SEQ + (jt + 2) * 64)) * HDIM + h * HD;
            #pragma unroll
            for (int j = 0; j < 2; j++) {
                int i = tid + j * 256;
                int r = i >> 3;
                int c8 = (i & 7) * 8;
                cp16(ks_base + st + (r * KS_STR + c8) * 2, Kg + (size_t)r * HDIM + c8);
                cp16(vs_base + st + (r * KS_STR + c8) * 2, Vg + (size_t)r * HDIM + c8);
            }
        }
        cp_commit();

        const uint32_t sk = ks_base + (jt % 3) * stage_b;
        const uint32_t sv = vs_base + (jt % 3) * stage_b;

        const bool active = (k0g <= q0 + wq + 15);
        if (active) {
            float sacc[8][4];
            #pragma unroll
            for (int j = 0; j < 8; j++)
                #pragma unroll
                for (int r = 0; r < 4; r++) sacc[j][r] = 0.f;

            #pragma unroll
            for (int ks = 0; ks < 4; ks++) {
                #pragma unroll
                for (int ng = 0; ng < 4; ng++) {
                    uint32_t b0, b1, b2, b3;
                    uint32_t addr = sk + ((ng * 16 + kn_row) * KS_STR + ks * 16 + kn_col) * 2;
                    ldsm_x4(b0, b1, b2, b3, addr);
                    uint32_t bf0[2] = {b0, b1}, bf1[2] = {b2, b3};
                    mma16816h(sacc[ng * 2],     qf[ks], bf0);
                    mma16816h(sacc[ng * 2 + 1], qf[ks], bf1);
                }
            }

            if (k0g + 63 > q0 + wq) {
                const int row0 = q0 + wq + g;
                const int row1 = row0 + 8;
                #pragma unroll
                for (int j = 0; j < 8; j++) {
                    const int col = k0g + j * 8 + t * 2;
                    if (col > row0)     sacc[j][0] = -1e30f;
                    if (col + 1 > row0) sacc[j][1] = -1e30f;
                    if (col > row1)     sacc[j][2] = -1e30f;
                    if (col + 1 > row1) sacc[j][3] = -1e30f;
                }
            }

            float tm0 = -1e30f, tm1 = -1e30f;
            #pragma unroll
            for (int j = 0; j < 8; j++) {
                tm0 = fmaxf(tm0, fmaxf(sacc[j][0], sacc[j][1]));
                tm1 = fmaxf(tm1, fmaxf(sacc[j][2], sacc[j][3]));
            }
            tm0 = fmaxf(tm0, __shfl_xor_sync(0xffffffffu, tm0, 1));
            tm0 = fmaxf(tm0, __shfl_xor_sync(0xffffffffu, tm0, 2));
            tm1 = fmaxf(tm1, __shfl_xor_sync(0xffffffffu, tm1, 1));
            tm1 = fmaxf(tm1, __shfl_xor_sync(0xffffffffu, tm1, 2));

            const float mn0 = fmaxf(m0r, tm0);
            const float mn1 = fmaxf(m1r, tm1);
            const float al0 = exp2f(m0r - mn0);
            const float al1 = exp2f(m1r - mn1);
            m0r = mn0; m1r = mn1;

            float rs0 = 0.f, rs1 = 0.f;
            #pragma unroll
            for (int j = 0; j < 8; j++) {
                sacc[j][0] = exp2f(sacc[j][0] - mn0);
                sacc[j][1] = exp2f(sacc[j][1] - mn0);
                sacc[j][2] = exp2f(sacc[j][2] - mn1);
                sacc[j][3] = exp2f(sacc[j][3] - mn1);
                rs0 += sacc[j][0] + sacc[j][1];
                rs1 += sacc[j][2] + sacc[j][3];
            }
            rs0 += __shfl_xor_sync(0xffffffffu, rs0, 1);
            rs0 += __shfl_xor_sync(0xffffffffu, rs0, 2);
            rs1 += __shfl_xor_sync(0xffffffffu, rs1, 1);
            rs1 += __shfl_xor_sync(0xffffffffu, rs1, 2);
            l0r = l0r * al0 + rs0;
            l1r = l1r * al1 + rs1;

            uint32_t pa[4][4];
            #pragma unroll
            for (int ks = 0; ks < 4; ks++) {
                __half2 h0 = __floats2half2_rn(sacc[2*ks][0],   sacc[2*ks][1]);
                __half2 h1 = __floats2half2_rn(sacc[2*ks][2],   sacc[2*ks][3]);
                __half2 h2 = __floats2half2_rn(sacc[2*ks+1][0], sacc[2*ks+1][1]);
                __half2 h3 = __floats2half2_rn(sacc[2*ks+1][2], sacc[2*ks+1][3]);
                pa[ks][0] = *(uint32_t*)&h0; pa[ks][1] = *(uint32_t*)&h1;
                pa[ks][2] = *(uint32_t*)&h2; pa[ks][3] = *(uint32_t*)&h3;
            }

            #pragma unroll
            for (int j = 0; j < 8; j++) {
                oacc[j][0] *= al0; oacc[j][1] *= al0;
                oacc[j][2] *= al1; oacc[j][3] *= al1;
            }
            #pragma unroll
            for (int ks = 0; ks < 4; ks++) {
                #pragma unroll
                for (int ng = 0; ng < 4; ng++) {
                    uint32_t b0, b1, b2, b3;
                    uint32_t addr = sv + ((ks * 16 + vk_row) * KS_STR + ng * 16 + vn_col) * 2;
                    ldsm_x4t(b0, b1, b2, b3, addr);
                    uint32_t bf0[2] = {b0, b1}, bf1[2] = {b2, b3};
                    mma16816h(oacc[ng * 2],     pa[ks], bf0);
                    mma16816h(oacc[ng * 2 + 1], pa[ks], bf1);
                }
            }
        }
    }

    const float il0 = 1.f / l0r;
    const float il1 = 1.f / l1r;
    __half* Og = O + ((size_t)(b * SEQ + q0 + wq)) * HDIM + h * HD;
    #pragma unroll
    for (int j = 0; j < 8; j++) {
        const int col = j * 8 + t * 2;
        *(__half2*)(Og + (size_t)g * HDIM + col) =
            __floats2half2_rn(oacc[j][0] * il0, oacc[j][1] * il0);
        *(__half2*)(Og + (size_t)(g + 8) * HDIM + col) =
            __floats2half2_rn(oacc[j][2] * il1, oacc[j][3] * il1);
    }
}

// ---------------- Residual + LayerNorm ---------------------------------------
__global__ void __launch_bounds__(256) ln_kernel(
    const float* __restrict__ X, const float* __restrict__ Y,
    const float* __restrict__ g, const float* __restrict__ be,
    float* __restrict__ out)
{
    const int row = blockIdx.x;
    const int tid = threadIdx.x;
    const float* xr = X + (size_t)row * HDIM;
    const float* yr = Y + (size_t)row * HDIM;

    float4 x4 = *(const float4*)(xr + tid * 4);
    float4 y4 = *(const float4*)(yr + tid * 4);
    float v0 = x4.x + y4.x, v1 = x4.y + y4.y, v2 = x4.z + y4.z, v3 = x4.w + y4.w;

    float s  = v0 + v1 + v2 + v3;
    float ss = v0 * v0 + v1 * v1 + v2 * v2 + v3 * v3;
    #pragma unroll
    for (int off = 16; off > 0; off >>= 1) {
        s  += __shfl_xor_sync(0xffffffffu, s, off);
        ss += __shfl_xor_sync(0xffffffffu, ss, off);
    }

    __shared__ float sbuf[8], ssbuf[8];
    __shared__ float mu_s, rstd_s;
    if ((tid & 31) == 0) { sbuf[tid >> 5] = s; ssbuf[tid >> 5] = ss; }
    __syncthreads();
    if (tid == 0) {
        float S = 0.f, SS = 0.f;
        #pragma unroll
        for (int k = 0; k < 8; k++) { S += sbuf[k]; SS += ssbuf[k]; }
        float mu = S * (1.0f / HDIM);
        float var = SS * (1.0f / HDIM) - mu * mu;
        mu_s = mu;
        rstd_s = rsqrtf(var + 1e-5f);
    }
    __syncthreads();
    float mu = mu_s, rs = rstd_s;

    float4 g4 = *(const float4*)(g + tid * 4);
    float4 b4 = *(const float4*)(be + tid * 4);
    float4 o;
    o.x = (v0 - mu) * rs * g4.x + b4.x;
    o.y = (v1 - mu) * rs * g4.y + b4.y;
    o.z = (v2 - mu) * rs * g4.z + b4.z;
    o.w = (v3 - mu) * rs * g4.w + b4.w;
    *(float4*)(out + (size_t)row * HDIM + tid * 4) = o;
}

// ---------------- launch -----------------------------------------------------
extern "C" void kernel_launch(void* const* d_in, const int* in_sizes, int n_in,
                              void* d_out, int out_size)
{
    const float* query = (const float*)d_in[0];
    const float* key   = (const float*)d_in[1];
    const float* value = (const float*)d_in[2];
    const float* Wq = (const float*)d_in[4];
    const float* bq = (const float*)d_in[5];
    const float* Wk = (const float*)d_in[6];
    const float* bk = (const float*)d_in[7];
    const float* Wv = (const float*)d_in[8];
    const float* bv = (const float*)d_in[9];
    const float* Wo = (const float*)d_in[10];
    const float* bo = (const float*)d_in[11];
    const float* lg = (const float*)d_in[12];
    const float* lb = (const float*)d_in[13];
    float* out = (float*)d_out;

    __half *dQh, *dKh, *dVh, *dAOh, *dqx, *dkx, *dvx, *dWq, *dWk, *dWv, *dWo;
    float *dY;
    cudaGetSymbolAddress((void**)&dQh, g_Qh);
    cudaGetSymbolAddress((void**)&dKh, g_Kh);
    cudaGetSymbolAddress((void**)&dVh, g_Vh);
    cudaGetSymbolAddress((void**)&dAOh, g_AOh);
    cudaGetSymbolAddress((void**)&dY,  g_Y);
    cudaGetSymbolAddress((void**)&dqx, g_qx);
    cudaGetSymbolAddress((void**)&dkx, g_kx);
    cudaGetSymbolAddress((void**)&dvx, g_vx);
    cudaGetSymbolAddress((void**)&dWq, g_Wqh);
    cudaGetSymbolAddress((void**)&dWk, g_Wkh);
    cudaGetSymbolAddress((void**)&dWv, g_Wvh);
    cudaGetSymbolAddress((void**)&dWo, g_Woh);

    const int nbig = MROWS * HDIM;
    const int nsmall = HDIM * HDIM;
    dim3 gCvt(nbig / (256 * 4), 7);
    cvt7<<<gCvt, 256>>>(query, key, value, Wq, Wk, Wv, Wo,
                        dqx, dkx, dvx, dWq, dWk, dWv, dWo, nbig, nsmall);

    cudaFuncSetAttribute(gemm_qkv, cudaFuncAttributeMaxDynamicSharedMemorySize, G_SMEM_BYTES);
    cudaFuncSetAttribute(gemm_o,   cudaFuncAttributeMaxDynamicSharedMemorySize, G_SMEM_BYTES);
    const int attn_smem = A_SMEM_HALVES * 2;
    cudaFuncSetAttribute(attn_fa, cudaFuncAttributeMaxDynamicSharedMemorySize, attn_smem);

    dim3 gQKV(HDIM / 128, MROWS / 256, 3);           // (8, 16, 3)
    gemm_qkv<<<gQKV, 512, G_SMEM_BYTES>>>(dqx, dkx, dvx, dWq, dWk, dWv,
                                          bq, bk, bv, dQh, dKh, dVh);

    attn_fa<<<dim3(SEQ / 128, NHEAD, BATCH), 256, attn_smem>>>(dQh, dKh, dVh, dAOh);

    dim3 gO(HDIM / 128, MROWS / 256);                // (8, 16)
    gemm_o<<<gO, 512, G_SMEM_BYTES>>>(dAOh, dWo, bo, dY);

    ln_kernel<<<MROWS, 256>>>(query, dY, lg, lb, out);
}